// round 12
// baseline (speedup 1.0000x reference)
#include <cuda_runtime.h>
#include <math.h>

#define NN 10000
#define NE 320000
#define EN 330000   // NE + NN self-loop slots
#define HH 256
#define NL 6
#define NHD 8
#define NG 16
#define DCAP 128    // per-warp smem alpha cache capacity

// ---------------- static device scratch ----------------
__device__ float g_h[NN * HH];
__device__ float g_xw[NN * HH];
__device__ float g_asrc[NN * NHD];
__device__ float g_adst[NN * NHD];
__device__ float g_alphaP[48 * EN];   // [layer*8+head][csr pos]
__device__ float g_u[48 * 32];
__device__ float g_uc[48];
__device__ int   g_deg[NN];
__device__ int   g_fill[NN];
__device__ int   g_off[NN + 1];
__device__ int   g_csrc[EN];
__device__ int   g_peid[EN];
__device__ int   g_gs[NG], g_ge[NG];
__device__ float g_xg[NG * 2 * HH];   // [g][mean(256) | sum(256)]

__device__ __forceinline__ float geluf(float x) {
    return 0.5f * x * (1.0f + erff(x * 0.70710678118654752f));
}

// ---------------- zero accumulators ----------------
__global__ void zero_kernel() {
    int i = blockIdx.x * blockDim.x + threadIdx.x;
    int stride = gridDim.x * blockDim.x;
    for (int j = i; j < NN; j += stride) { g_deg[j] = 0; g_fill[j] = 0; }
    if (i < NG) { g_gs[i] = 0; g_ge[i] = 0; }
}

// ---------------- CSR build (by destination) ----------------
__global__ void deg_kernel(const int* __restrict__ ei) {
    int e = blockIdx.x * blockDim.x + threadIdx.x;
    if (e < NE) atomicAdd(&g_deg[ei[NE + e]], 1);
}

__global__ void scan_kernel() {
    __shared__ int s[1024];
    int t = threadIdx.x;
    int d[10];
    int loc = 0;
#pragma unroll
    for (int j = 0; j < 10; j++) {
        int n = t * 10 + j;
        int v = (n < NN) ? (g_deg[n] + 1) : 0;   // +1 self-loop slot
        d[j] = v; loc += v;
    }
    s[t] = loc; __syncthreads();
    for (int off = 1; off < 1024; off <<= 1) {
        int v = (t >= off) ? s[t - off] : 0;
        __syncthreads();
        s[t] += v;
        __syncthreads();
    }
    int ex = s[t] - loc;
#pragma unroll
    for (int j = 0; j < 10; j++) {
        int n = t * 10 + j;
        if (n < NN) g_off[n] = ex;
        ex += d[j];
    }
    if (t == 1023) g_off[NN] = s[1023];
}

__global__ void fill_kernel(const int* __restrict__ ei) {
    int e = blockIdx.x * blockDim.x + threadIdx.x;
    if (e >= NE) return;
    int d = ei[NE + e];
    int pos = g_off[d] + atomicAdd(&g_fill[d], 1);
    g_csrc[pos] = ei[e];
    g_peid[pos] = e;
}

__global__ void loopslot_kernel() {
    int n = blockIdx.x * blockDim.x + threadIdx.x;
    if (n >= NN) return;
    int pos = g_off[n + 1] - 1;
    g_csrc[pos] = n;
    g_peid[pos] = NE + n;
}

// ------- contracted edge weights: u[i,h,f] = ((att_edge slice @ lin_edge_w slice) @ eew) -------
__global__ void u_kernel(const float* __restrict__ att_edge,
                         const float* __restrict__ lin_edge_w,
                         const float* __restrict__ eew,
                         const float* __restrict__ eeb) {
    int comb = blockIdx.x;          // layer*8 + head
    int i = comb >> 3, hd = comb & 7;
    int tid = threadIdx.x;          // 256 threads
    __shared__ float sae[32];
    __shared__ float sv[256];
    if (tid < 32) sae[tid] = att_edge[i * 256 + hd * 32 + tid];
    __syncthreads();
    const float* lw = lin_edge_w + (size_t)i * 65536 + (size_t)(hd * 32) * 256 + tid;
    float v = 0.f;
#pragma unroll
    for (int o = 0; o < 32; o++) v = fmaf(sae[o], lw[(size_t)o * 256], v);
    sv[tid] = v; __syncthreads();
    if (tid < 32) {
        float u = 0.f;
        for (int c = 0; c < 256; c++) u = fmaf(sv[c], eew[c * 32 + tid], u);
        g_u[comb * 32 + tid] = u;
    }
    if (tid == 255) {
        float s = 0.f;
        for (int c = 0; c < 256; c++) s = fmaf(sv[c], eeb[c], s);
        g_uc[comb] = s;
    }
}

// ------- per-edge attr attention term for all 48 (layer,head) in CSR order -------
__global__ __launch_bounds__(128) void alphaP_kernel(const float* __restrict__ edge_attr) {
    __shared__ float su[48 * 32];
    __shared__ float suc[48];
    int tid = threadIdx.x;
    for (int j = tid; j < 48 * 32; j += 128) su[j] = g_u[j];
    if (tid < 48) suc[tid] = g_uc[tid];
    __syncthreads();
    int pos = blockIdx.x * 128 + tid;
    if (pos >= EN) return;
    int e = g_peid[pos];
    if (e >= NE) return;          // self-loop slot written by loopdiv_kernel
    float ea[32];
    const float4* p = (const float4*)(edge_attr + (size_t)e * 32);
#pragma unroll
    for (int q = 0; q < 8; q++) {
        float4 v = p[q];
        ea[4 * q] = v.x; ea[4 * q + 1] = v.y; ea[4 * q + 2] = v.z; ea[4 * q + 3] = v.w;
    }
#pragma unroll 2
    for (int c = 0; c < 48; c++) {
        const float4* u4 = (const float4*)&su[c * 32];
        float a0 = suc[c], a1 = 0.f, a2 = 0.f, a3 = 0.f;
#pragma unroll
        for (int q = 0; q < 8; q++) {
            float4 uu = u4[q];
            a0 = fmaf(ea[4 * q], uu.x, a0);
            a1 = fmaf(ea[4 * q + 1], uu.y, a1);
            a2 = fmaf(ea[4 * q + 2], uu.z, a2);
            a3 = fmaf(ea[4 * q + 3], uu.w, a3);
        }
        g_alphaP[(size_t)c * EN + pos] = (a0 + a1) + (a2 + a3);
    }
}

// ------- self-loop 'mean' slot: segment mean of alphaP over incoming edges (no atomics) -------
__global__ __launch_bounds__(256) void loopdiv_kernel() {
    int n = blockIdx.x;
    int wid = threadIdx.x >> 5, lane = threadIdx.x & 31;
    int beg = g_off[n], last = g_off[n + 1] - 1;   // [beg,last) are real edges
    float invc = 1.f / fmaxf((float)(last - beg), 1.f);
    for (int c = wid; c < 48; c += 8) {
        const float* ap = g_alphaP + (size_t)c * EN;
        float s = 0.f;
        for (int j = beg + lane; j < last; j += 32) s += ap[j];
#pragma unroll
        for (int o = 16; o > 0; o >>= 1) s += __shfl_xor_sync(0xffffffffu, s, o);
        if (lane == 0) g_alphaP[(size_t)c * EN + last] = s * invc;
    }
}

// ---------------- fp32 GEMM (plain FFMA): C[M,256] = A[M,K] @ B[256,K]^T (+bias) ----------------
__global__ __launch_bounds__(256) void gemm_nt(const float* __restrict__ A,
                                               const float* __restrict__ B,
                                               const float* __restrict__ bias,
                                               float* __restrict__ C,
                                               int M, int K) {
    __shared__ float As[32][132];
    __shared__ float Bs[32][68];
    int mBase = blockIdx.x * 128, nBase = blockIdx.y * 64;
    int tid = threadIdx.x;
    int tx = tid & 15, ty = tid >> 4;
    float acc[8][4];
#pragma unroll
    for (int i = 0; i < 8; i++)
#pragma unroll
        for (int j = 0; j < 4; j++) acc[i][j] = 0.f;

    for (int kb = 0; kb < K; kb += 32) {
#pragma unroll
        for (int i = 0; i < 4; i++) {
            int id = tid + i * 256;
            int row = id >> 3;
            int kc = (id & 7) << 2;
            float4 v = make_float4(0.f, 0.f, 0.f, 0.f);
            int gm = mBase + row;
            if (gm < M) v = *(const float4*)(A + (size_t)gm * K + kb + kc);
            As[kc][row] = v.x; As[kc + 1][row] = v.y;
            As[kc + 2][row] = v.z; As[kc + 3][row] = v.w;
        }
#pragma unroll
        for (int i = 0; i < 2; i++) {
            int id = tid + i * 256;
            int row = id >> 3;
            int kc = (id & 7) << 2;
            float4 v = *(const float4*)(B + (size_t)(nBase + row) * K + kb + kc);
            Bs[kc][row] = v.x; Bs[kc + 1][row] = v.y;
            Bs[kc + 2][row] = v.z; Bs[kc + 3][row] = v.w;
        }
        __syncthreads();
#pragma unroll
        for (int k = 0; k < 32; k++) {
            float4 a0 = *(const float4*)&As[k][ty * 8];
            float4 a1 = *(const float4*)&As[k][ty * 8 + 4];
            float4 b0 = *(const float4*)&Bs[k][tx * 4];
            float a[8] = {a0.x, a0.y, a0.z, a0.w, a1.x, a1.y, a1.z, a1.w};
            float b[4] = {b0.x, b0.y, b0.z, b0.w};
#pragma unroll
            for (int i = 0; i < 8; i++)
#pragma unroll
                for (int j = 0; j < 4; j++) acc[i][j] = fmaf(a[i], b[j], acc[i][j]);
        }
        __syncthreads();
    }
#pragma unroll
    for (int i = 0; i < 8; i++) {
        int gm = mBase + ty * 8 + i;
        if (gm >= M) continue;
#pragma unroll
        for (int j = 0; j < 4; j++) {
            int gn = nBase + tx * 4 + j;
            float v = acc[i][j];
            if (bias) v += bias[gn];
            C[(size_t)gm * HH + gn] = v;
        }
    }
}

// ---------------- per-node attention scalars ----------------
__global__ void asrc_kernel(int layer,
                            const float* __restrict__ attS,
                            const float* __restrict__ attD) {
    int idx = blockIdx.x * blockDim.x + threadIdx.x;
    if (idx >= NN * NHD) return;
    int n = idx >> 3, hd = idx & 7;
    const float* xr = g_xw + (size_t)n * HH + hd * 32;
    const float* aS = attS + layer * 256 + hd * 32;
    const float* aD = attD + layer * 256 + hd * 32;
    float s = 0.f, d = 0.f;
#pragma unroll
    for (int o = 0; o < 32; o++) {
        float xv = xr[o];
        s = fmaf(xv, aS[o], s);
        d = fmaf(xv, aD[o], d);
    }
    g_asrc[idx] = s;
    g_adst[idx] = d;
}

// --------- fused alpha + softmax + aggregate + bias + LayerNorm + GELU + residual ---------
// pass1: compute leaky(asrc[src]+adst[n]+alphaP) on the fly (coalesced alphaP read),
//        cache in smem (cap DCAP per warp), track segment max.
// pass2: serial gather with __expf from smem cache (recompute fallback if deg > DCAP).
__global__ __launch_bounds__(256) void agg_kernel(int layer,
                                                  const float* __restrict__ convb,
                                                  const float* __restrict__ lng,
                                                  const float* __restrict__ lnb) {
    __shared__ float sbuf[NHD][DCAP];
    __shared__ float red[256];
    int n = blockIdx.x, tid = threadIdx.x;
    int hd = tid >> 5, lane = tid & 31;
    int beg = g_off[n], end = g_off[n + 1];
    int deg = end - beg;
    const float* aP = g_alphaP + (size_t)(layer * 8 + hd) * EN;
    float adst = g_adst[n * NHD + hd];

    // pass 1
    float m = -3.0e38f;
    for (int j = beg + lane; j < end; j += 32) {
        float a = g_asrc[(size_t)g_csrc[j] * NHD + hd] + adst + aP[j];
        a = a > 0.f ? a : 0.2f * a;
        int o = j - beg;
        if (o < DCAP) sbuf[hd][o] = a;
        m = fmaxf(m, a);
    }
#pragma unroll
    for (int o = 16; o > 0; o >>= 1) m = fmaxf(m, __shfl_xor_sync(0xffffffffu, m, o));
    __syncwarp();

    // pass 2
    float s = 0.f, acc = 0.f;
    const float* xwp = g_xw + hd * 32 + lane;
    if (deg <= DCAP) {
        for (int j = beg; j < end; j++) {
            float e = __expf(sbuf[hd][j - beg] - m);
            int src = g_csrc[j];
            s += e;
            acc = fmaf(e, xwp[(size_t)src * HH], acc);
        }
    } else {
        for (int j = beg; j < end; j++) {
            int src = g_csrc[j];
            float a = g_asrc[(size_t)src * NHD + hd] + adst + aP[j];
            a = a > 0.f ? a : 0.2f * a;
            float e = __expf(a - m);
            s += e;
            acc = fmaf(e, xwp[(size_t)src * HH], acc);
        }
    }
    acc *= 1.f / (s + 1e-16f);

    float v = acc + convb[layer * HH + tid];
    red[tid] = v; __syncthreads();
#pragma unroll
    for (int st = 128; st > 0; st >>= 1) {
        if (tid < st) red[tid] += red[tid + st];
        __syncthreads();
    }
    float mu = red[0] * (1.f / 256.f);
    __syncthreads();
    float dv = v - mu;
    red[tid] = dv * dv; __syncthreads();
#pragma unroll
    for (int st = 128; st > 0; st >>= 1) {
        if (tid < st) red[tid] += red[tid + st];
        __syncthreads();
    }
    float var = red[0] * (1.f / 256.f);
    float y = lng[layer * HH + tid] * dv * rsqrtf(var + 1e-5f) + lnb[layer * HH + tid];
    float gv = geluf(y);
    float hn = (layer > 0) ? (gv + g_h[(size_t)n * HH + tid]) : gv;
    g_h[(size_t)n * HH + tid] = hn;
}

// ---------------- graph pooling (sorted batch -> ranges, no atomics) ----------------
__global__ void bounds_kernel(const int* __restrict__ batch) {
    int n = blockIdx.x * blockDim.x + threadIdx.x;
    if (n >= NN) return;
    int b = batch[n];
    if (n == 0 || batch[n - 1] != b) g_gs[b] = n;
    if (n == NN - 1 || batch[n + 1] != b) g_ge[b] = n + 1;
}

__global__ __launch_bounds__(256) void pool_kernel() {
    int g = blockIdx.x, t = threadIdx.x;
    int beg = g_gs[g], end = g_ge[g];
    float s = 0.f;
    for (int n = beg; n < end; n++) s += g_h[(size_t)n * HH + t];
    float cnt = (float)(end - beg);
    g_xg[g * 512 + t] = s / fmaxf(cnt, 1.f);
    g_xg[g * 512 + 256 + t] = s;
}

// ---------------- MLP heads ----------------
__global__ __launch_bounds__(256) void mlp_kernel(
    const float* __restrict__ pw1, const float* __restrict__ pb1,
    const float* __restrict__ pw2, const float* __restrict__ pb2,
    const float* __restrict__ pw3, const float* __restrict__ pb3,
    const float* __restrict__ mw1, const float* __restrict__ mb1,
    const float* __restrict__ mw2, const float* __restrict__ mb2,
    const float* __restrict__ mw3, const float* __restrict__ mb3,
    float* __restrict__ out) {
    int g = blockIdx.x & 15;
    int head = blockIdx.x >> 4;
    const float* w1 = head ? mw1 : pw1; const float* b1 = head ? mb1 : pb1;
    const float* w2 = head ? mw2 : pw2; const float* b2 = head ? mb2 : pb2;
    const float* w3 = head ? mw3 : pw3; const float* b3 = head ? mb3 : pb3;
    int t = threadIdx.x;
    __shared__ float sx[512];
    __shared__ float h1[256];
    __shared__ float h2[128];
    sx[t] = g_xg[g * 512 + t];
    sx[t + 256] = g_xg[g * 512 + 256 + t];
    __syncthreads();
    {
        const float* wr = w1 + (size_t)t * 512;
        float a = b1[t];
        for (int k = 0; k < 512; k++) a = fmaf(sx[k], wr[k], a);
        h1[t] = geluf(a);
    }
    __syncthreads();
    if (t < 128) {
        const float* wr = w2 + (size_t)t * 256;
        float a = b2[t];
        for (int k = 0; k < 256; k++) a = fmaf(h1[k], wr[k], a);
        h2[t] = geluf(a);
    }
    __syncthreads();
    if (t < 3) {
        const float* wr = w3 + (size_t)t * 128;
        float a = b3[t];
        for (int k = 0; k < 128; k++) a = fmaf(h2[k], wr[k], a);
        out[head * 48 + g * 3 + t] = 1.f / (1.f + expf(-a));
    }
}

// ---------------- launcher ----------------
extern "C" void kernel_launch(void* const* d_in, const int* in_sizes, int n_in,
                              void* d_out, int out_size) {
    const float* x          = (const float*)d_in[0];
    const int*   edge_index = (const int*)d_in[1];
    const float* edge_attr  = (const float*)d_in[2];
    const int*   batch      = (const int*)d_in[3];
    const float* node_w     = (const float*)d_in[4];
    const float* node_b     = (const float*)d_in[5];
    const float* eew        = (const float*)d_in[6];
    const float* eeb        = (const float*)d_in[7];
    const float* lin_w      = (const float*)d_in[8];
    const float* att_src    = (const float*)d_in[9];
    const float* att_dst    = (const float*)d_in[10];
    const float* att_edge   = (const float*)d_in[11];
    const float* lin_edge_w = (const float*)d_in[12];
    const float* conv_b     = (const float*)d_in[13];
    const float* ln_g       = (const float*)d_in[14];
    const float* ln_b       = (const float*)d_in[15];
    const float* pw1 = (const float*)d_in[16]; const float* pb1 = (const float*)d_in[17];
    const float* pw2 = (const float*)d_in[18]; const float* pb2 = (const float*)d_in[19];
    const float* pw3 = (const float*)d_in[20]; const float* pb3 = (const float*)d_in[21];
    const float* mw1 = (const float*)d_in[22]; const float* mb1 = (const float*)d_in[23];
    const float* mw2 = (const float*)d_in[24]; const float* mb2 = (const float*)d_in[25];
    const float* mw3 = (const float*)d_in[26]; const float* mb3 = (const float*)d_in[27];
    float* out = (float*)d_out;

    // setup
    zero_kernel<<<64, 256>>>();
    deg_kernel<<<(NE + 255) / 256, 256>>>(edge_index);
    scan_kernel<<<1, 1024>>>();
    fill_kernel<<<(NE + 255) / 256, 256>>>(edge_index);
    loopslot_kernel<<<(NN + 255) / 256, 256>>>();
    u_kernel<<<48, 256>>>(att_edge, lin_edge_w, eew, eeb);
    alphaP_kernel<<<(EN + 127) / 128, 128>>>(edge_attr);
    loopdiv_kernel<<<NN, 256>>>();
    bounds_kernel<<<(NN + 255) / 256, 256>>>(batch);

    float *d_h, *d_xw;
    cudaGetSymbolAddress((void**)&d_h, g_h);
    cudaGetSymbolAddress((void**)&d_xw, g_xw);

    // node embedding: h = x @ node_w^T + node_b
    {
        dim3 grid((NN + 127) / 128, HH / 64);
        gemm_nt<<<grid, 256>>>(x, node_w, node_b, d_h, NN, 64);
    }

    for (int layer = 0; layer < NL; layer++) {
        dim3 grid((NN + 127) / 128, HH / 64);
        gemm_nt<<<grid, 256>>>(d_h, lin_w + (size_t)layer * 65536, nullptr, d_xw, NN, 256);
        asrc_kernel<<<(NN * NHD + 255) / 256, 256>>>(layer, att_src, att_dst);
        agg_kernel<<<NN, 256>>>(layer, conv_b, ln_g, ln_b);
    }

    pool_kernel<<<NG, 256>>>();
    mlp_kernel<<<32, 256>>>(pw1, pb1, pw2, pb2, pw3, pb3,
                            mw1, mb1, mw2, mb2, mw3, mb3, out);
}

// round 13
// speedup vs baseline: 1.7511x; 1.7511x over previous
#include <cuda_runtime.h>
#include <math.h>
#include <stdint.h>

#define NN 10000
#define NE 320000
#define EN 330000   // NE + NN self-loop slots
#define HH 256
#define NL 6
#define NHD 8
#define NG 16

// ---------------- static device scratch ----------------
__device__ float g_h[NN * HH];
__device__ float g_xw[NN * HH];
__device__ float g_asrc[NN * NHD];
__device__ float g_adst[NN * NHD];
__device__ float g_alphaP[48 * EN];   // [layer*8+head][csr pos]
__device__ float g_alphaF[NHD * EN];  // [head][csr pos], current layer
__device__ float g_u[48 * 32];
__device__ float g_uc[48];
__device__ int   g_deg[NN];
__device__ int   g_fill[NN];
__device__ int   g_off[NN + 1];
__device__ int   g_csrc[EN];
__device__ int   g_peid[EN];
__device__ int   g_pnode[EN];
__device__ int   g_gs[NG], g_ge[NG];
__device__ float g_xg[NG * 2 * HH];   // [g][mean(256) | sum(256)]

__device__ __forceinline__ float geluf(float x) {
    return 0.5f * x * (1.0f + erff(x * 0.70710678118654752f));
}

__device__ __forceinline__ uint32_t f2tf(float f) {
    uint32_t r;
    asm("cvt.rna.tf32.f32 %0, %1;" : "=r"(r) : "f"(f));
    return r;
}

// ---------------- zero accumulators ----------------
__global__ void zero_kernel() {
    int i = blockIdx.x * blockDim.x + threadIdx.x;
    int stride = gridDim.x * blockDim.x;
    for (int j = i; j < NN; j += stride) { g_deg[j] = 0; g_fill[j] = 0; }
    if (i < NG) { g_gs[i] = 0; g_ge[i] = 0; }
}

// ---------------- CSR build (by destination) ----------------
__global__ void deg_kernel(const int* __restrict__ ei) {
    int e = blockIdx.x * blockDim.x + threadIdx.x;
    if (e < NE) atomicAdd(&g_deg[ei[NE + e]], 1);
}

__global__ void scan_kernel() {
    __shared__ int s[1024];
    int t = threadIdx.x;
    int d[10];
    int loc = 0;
#pragma unroll
    for (int j = 0; j < 10; j++) {
        int n = t * 10 + j;
        int v = (n < NN) ? (g_deg[n] + 1) : 0;   // +1 self-loop slot
        d[j] = v; loc += v;
    }
    s[t] = loc; __syncthreads();
    for (int off = 1; off < 1024; off <<= 1) {
        int v = (t >= off) ? s[t - off] : 0;
        __syncthreads();
        s[t] += v;
        __syncthreads();
    }
    int ex = s[t] - loc;
#pragma unroll
    for (int j = 0; j < 10; j++) {
        int n = t * 10 + j;
        if (n < NN) g_off[n] = ex;
        ex += d[j];
    }
    if (t == 1023) g_off[NN] = s[1023];
}

__global__ void fill_kernel(const int* __restrict__ ei) {
    int e = blockIdx.x * blockDim.x + threadIdx.x;
    if (e >= NE) return;
    int d = ei[NE + e];
    int pos = g_off[d] + atomicAdd(&g_fill[d], 1);
    g_csrc[pos] = ei[e];
    g_peid[pos] = e;
    g_pnode[pos] = d;
}

__global__ void loopslot_kernel() {
    int n = blockIdx.x * blockDim.x + threadIdx.x;
    if (n >= NN) return;
    int pos = g_off[n + 1] - 1;
    g_csrc[pos] = n;
    g_peid[pos] = NE + n;
    g_pnode[pos] = n;
}

// ------- contracted edge weights: u[i,h,f] = ((att_edge slice @ lin_edge_w slice) @ eew) -------
__global__ void u_kernel(const float* __restrict__ att_edge,
                         const float* __restrict__ lin_edge_w,
                         const float* __restrict__ eew,
                         const float* __restrict__ eeb) {
    int comb = blockIdx.x;          // layer*8 + head
    int i = comb >> 3, hd = comb & 7;
    int tid = threadIdx.x;          // 256 threads
    __shared__ float sae[32];
    __shared__ float sv[256];
    if (tid < 32) sae[tid] = att_edge[i * 256 + hd * 32 + tid];
    __syncthreads();
    const float* lw = lin_edge_w + (size_t)i * 65536 + (size_t)(hd * 32) * 256 + tid;
    float v = 0.f;
#pragma unroll
    for (int o = 0; o < 32; o++) v = fmaf(sae[o], lw[(size_t)o * 256], v);
    sv[tid] = v; __syncthreads();
    if (tid < 32) {
        float u = 0.f;
        for (int c = 0; c < 256; c++) u = fmaf(sv[c], eew[c * 32 + tid], u);
        g_u[comb * 32 + tid] = u;
    }
    if (tid == 255) {
        float s = 0.f;
        for (int c = 0; c < 256; c++) s = fmaf(sv[c], eeb[c], s);
        g_uc[comb] = s;
    }
}

// ------- per-edge attr attention term for all 48 (layer,head) in CSR order -------
__global__ __launch_bounds__(128) void alphaP_kernel(const float* __restrict__ edge_attr) {
    __shared__ float su[48 * 32];
    __shared__ float suc[48];
    int tid = threadIdx.x;
    for (int j = tid; j < 48 * 32; j += 128) su[j] = g_u[j];
    if (tid < 48) suc[tid] = g_uc[tid];
    __syncthreads();
    int pos = blockIdx.x * 128 + tid;
    if (pos >= EN) return;
    int e = g_peid[pos];
    if (e >= NE) return;          // self-loop slot written by loopdiv_kernel
    float ea[32];
    const float4* p = (const float4*)(edge_attr + (size_t)e * 32);
#pragma unroll
    for (int q = 0; q < 8; q++) {
        float4 v = p[q];
        ea[4 * q] = v.x; ea[4 * q + 1] = v.y; ea[4 * q + 2] = v.z; ea[4 * q + 3] = v.w;
    }
#pragma unroll 2
    for (int c = 0; c < 48; c++) {
        const float4* u4 = (const float4*)&su[c * 32];
        float a0 = suc[c], a1 = 0.f, a2 = 0.f, a3 = 0.f;
#pragma unroll
        for (int q = 0; q < 8; q++) {
            float4 uu = u4[q];
            a0 = fmaf(ea[4 * q], uu.x, a0);
            a1 = fmaf(ea[4 * q + 1], uu.y, a1);
            a2 = fmaf(ea[4 * q + 2], uu.z, a2);
            a3 = fmaf(ea[4 * q + 3], uu.w, a3);
        }
        g_alphaP[(size_t)c * EN + pos] = (a0 + a1) + (a2 + a3);
    }
}

// ------- self-loop 'mean' slot: segment mean of alphaP over incoming edges (no atomics) -------
__global__ __launch_bounds__(256) void loopdiv_kernel() {
    int n = blockIdx.x;
    int wid = threadIdx.x >> 5, lane = threadIdx.x & 31;
    int beg = g_off[n], last = g_off[n + 1] - 1;   // [beg,last) are real edges
    float invc = 1.f / fmaxf((float)(last - beg), 1.f);
    for (int c = wid; c < 48; c += 8) {
        const float* ap = g_alphaP + (size_t)c * EN;
        float s = 0.f;
        for (int j = beg + lane; j < last; j += 32) s += ap[j];
#pragma unroll
        for (int o = 16; o > 0; o >>= 1) s += __shfl_xor_sync(0xffffffffu, s, o);
        if (lane == 0) g_alphaP[(size_t)c * EN + last] = s * invc;
    }
}

// ---------------- tf32 tensor-core GEMM: C[M,256] = A[M,K] @ B[256,K]^T (+bias) ----------------
// Block tile 128m x 128n, 8 warps of 64m x 32n each. K staged in chunks of 32.
// smem m/n-major with row pad 36 (fragment LDS provably conflict-free: bank = 4*g + tig).
__global__ __launch_bounds__(256) void gemm_nt(const float* __restrict__ A,
                                               const float* __restrict__ B,
                                               const float* __restrict__ bias,
                                               float* __restrict__ C,
                                               int M, int K) {
    __shared__ uint32_t As2[128 * 36];
    __shared__ uint32_t Bs2[128 * 36];
    int mBase = blockIdx.x * 128, nBase = blockIdx.y * 128;
    int tid = threadIdx.x;
    int warpId = tid >> 5, lane = tid & 31;
    int wm = warpId & 1, wn = warpId >> 1;        // 2 x 4 warp grid
    int g = lane >> 2, tig = lane & 3;

    float c[4][4][4];                              // [mt][nt][frag]
#pragma unroll
    for (int mt = 0; mt < 4; mt++)
#pragma unroll
        for (int nt = 0; nt < 4; nt++)
#pragma unroll
            for (int q = 0; q < 4; q++) c[mt][nt][q] = 0.f;

    for (int kb = 0; kb < K; kb += 32) {
        // stage A (convert to tf32 once)
#pragma unroll
        for (int i = 0; i < 4; i++) {
            int id = tid + i * 256;
            int row = id >> 3;
            int kc = (id & 7) << 2;
            float4 v = make_float4(0.f, 0.f, 0.f, 0.f);
            int gm = mBase + row;
            if (gm < M) v = *(const float4*)(A + (size_t)gm * K + kb + kc);
            uint4 t = make_uint4(f2tf(v.x), f2tf(v.y), f2tf(v.z), f2tf(v.w));
            *(uint4*)&As2[row * 36 + kc] = t;
        }
        // stage B
#pragma unroll
        for (int i = 0; i < 4; i++) {
            int id = tid + i * 256;
            int row = id >> 3;
            int kc = (id & 7) << 2;
            float4 v = *(const float4*)(B + (size_t)(nBase + row) * K + kb + kc);
            uint4 t = make_uint4(f2tf(v.x), f2tf(v.y), f2tf(v.z), f2tf(v.w));
            *(uint4*)&Bs2[row * 36 + kc] = t;
        }
        __syncthreads();

#pragma unroll
        for (int k8 = 0; k8 < 4; k8++) {
            int k0 = k8 * 8;
            uint32_t a[4][4], b[4][2];
#pragma unroll
            for (int mt = 0; mt < 4; mt++) {
                int r0 = (wm * 64 + mt * 16 + g) * 36;
                int r1 = (wm * 64 + mt * 16 + 8 + g) * 36;
                a[mt][0] = As2[r0 + k0 + tig];
                a[mt][1] = As2[r1 + k0 + tig];
                a[mt][2] = As2[r0 + k0 + tig + 4];
                a[mt][3] = As2[r1 + k0 + tig + 4];
            }
#pragma unroll
            for (int nt = 0; nt < 4; nt++) {
                int rn = (wn * 32 + nt * 8 + g) * 36;
                b[nt][0] = Bs2[rn + k0 + tig];
                b[nt][1] = Bs2[rn + k0 + tig + 4];
            }
#pragma unroll
            for (int mt = 0; mt < 4; mt++)
#pragma unroll
                for (int nt = 0; nt < 4; nt++) {
                    asm volatile(
                        "mma.sync.aligned.m16n8k8.row.col.f32.tf32.tf32.f32 "
                        "{%0,%1,%2,%3}, {%4,%5,%6,%7}, {%8,%9}, {%0,%1,%2,%3};"
                        : "+f"(c[mt][nt][0]), "+f"(c[mt][nt][1]),
                          "+f"(c[mt][nt][2]), "+f"(c[mt][nt][3])
                        : "r"(a[mt][0]), "r"(a[mt][1]), "r"(a[mt][2]), "r"(a[mt][3]),
                          "r"(b[nt][0]), "r"(b[nt][1]));
                }
        }
        __syncthreads();
    }

    // epilogue
#pragma unroll
    for (int mt = 0; mt < 4; mt++) {
        int r0 = mBase + wm * 64 + mt * 16 + g;
        int r1 = r0 + 8;
#pragma unroll
        for (int nt = 0; nt < 4; nt++) {
            int cn = nBase + wn * 32 + nt * 8 + 2 * tig;
            float b0 = 0.f, b1 = 0.f;
            if (bias) { b0 = bias[cn]; b1 = bias[cn + 1]; }
            if (r0 < M) {
                float2 v = make_float2(c[mt][nt][0] + b0, c[mt][nt][1] + b1);
                *(float2*)(C + (size_t)r0 * HH + cn) = v;
            }
            if (r1 < M) {
                float2 v = make_float2(c[mt][nt][2] + b0, c[mt][nt][3] + b1);
                *(float2*)(C + (size_t)r1 * HH + cn) = v;
            }
        }
    }
}

// ---------------- per-node attention scalars ----------------
__global__ void asrc_kernel(int layer,
                            const float* __restrict__ attS,
                            const float* __restrict__ attD) {
    int idx = blockIdx.x * blockDim.x + threadIdx.x;
    if (idx >= NN * NHD) return;
    int n = idx >> 3, hd = idx & 7;
    const float* xr = g_xw + (size_t)n * HH + hd * 32;
    const float* aS = attS + layer * 256 + hd * 32;
    const float* aD = attD + layer * 256 + hd * 32;
    float s = 0.f, d = 0.f;
#pragma unroll
    for (int o = 0; o < 32; o++) {
        float xv = xr[o];
        s = fmaf(xv, aS[o], s);
        d = fmaf(xv, aD[o], d);
    }
    g_asrc[idx] = s;
    g_adst[idx] = d;
}

// ---------------- full leaky-relu'd alpha per CSR slot ----------------
__global__ void alphaF_kernel(int layer) {
    int pos = blockIdx.x * blockDim.x + threadIdx.x;
    if (pos >= EN) return;
    int src = g_csrc[pos];
    int nd  = g_pnode[pos];
    const float4* sa = (const float4*)(g_asrc + (size_t)src * 8);
    const float4* da = (const float4*)(g_adst + (size_t)nd * 8);
    float4 s0 = sa[0], s1 = sa[1], d0 = da[0], d1 = da[1];
    float as[8] = {s0.x, s0.y, s0.z, s0.w, s1.x, s1.y, s1.z, s1.w};
    float ad[8] = {d0.x, d0.y, d0.z, d0.w, d1.x, d1.y, d1.z, d1.w};
#pragma unroll
    for (int hd = 0; hd < 8; hd++) {
        float a = as[hd] + ad[hd] + g_alphaP[(size_t)(layer * 8 + hd) * EN + pos];
        a = a > 0.f ? a : 0.2f * a;
        g_alphaF[(size_t)hd * EN + pos] = a;
    }
}

// --------- fused softmax + aggregate + bias + LayerNorm + GELU + residual ---------
__global__ __launch_bounds__(256) void agg_kernel(int layer,
                                                  const float* __restrict__ convb,
                                                  const float* __restrict__ lng,
                                                  const float* __restrict__ lnb) {
    int n = blockIdx.x, tid = threadIdx.x;
    int hd = tid >> 5, lane = tid & 31;
    int beg = g_off[n], end = g_off[n + 1];
    const float* aF = g_alphaF + (size_t)hd * EN;

    // pass 1: segment max
    float m = -3.0e38f;
    for (int j = beg + lane; j < end; j += 32) m = fmaxf(m, aF[j]);
#pragma unroll
    for (int o = 16; o > 0; o >>= 1) m = fmaxf(m, __shfl_xor_sync(0xffffffffu, m, o));

    // pass 2: fused denominator + gather (unnormalized), fast exp
    float s = 0.f, acc = 0.f;
    const float* xwp = g_xw + hd * 32 + lane;
    for (int j = beg; j < end; j++) {
        float e = __expf(aF[j] - m);
        int src = g_csrc[j];
        s += e;
        acc = fmaf(e, xwp[(size_t)src * HH], acc);
    }
    acc *= 1.f / (s + 1e-16f);

    float v = acc + convb[layer * HH + tid];
    __shared__ float red[256];
    red[tid] = v; __syncthreads();
#pragma unroll
    for (int st = 128; st > 0; st >>= 1) {
        if (tid < st) red[tid] += red[tid + st];
        __syncthreads();
    }
    float mu = red[0] * (1.f / 256.f);
    __syncthreads();
    float dv = v - mu;
    red[tid] = dv * dv; __syncthreads();
#pragma unroll
    for (int st = 128; st > 0; st >>= 1) {
        if (tid < st) red[tid] += red[tid + st];
        __syncthreads();
    }
    float var = red[0] * (1.f / 256.f);
    float y = lng[layer * HH + tid] * dv * rsqrtf(var + 1e-5f) + lnb[layer * HH + tid];
    float gv = geluf(y);
    float hn = (layer > 0) ? (gv + g_h[(size_t)n * HH + tid]) : gv;
    g_h[(size_t)n * HH + tid] = hn;
}

// ---------------- graph pooling (sorted batch -> ranges, no atomics) ----------------
__global__ void bounds_kernel(const int* __restrict__ batch) {
    int n = blockIdx.x * blockDim.x + threadIdx.x;
    if (n >= NN) return;
    int b = batch[n];
    if (n == 0 || batch[n - 1] != b) g_gs[b] = n;
    if (n == NN - 1 || batch[n + 1] != b) g_ge[b] = n + 1;
}

__global__ __launch_bounds__(256) void pool_kernel() {
    int g = blockIdx.x, t = threadIdx.x;
    int beg = g_gs[g], end = g_ge[g];
    float s = 0.f;
    for (int n = beg; n < end; n++) s += g_h[(size_t)n * HH + t];
    float cnt = (float)(end - beg);
    g_xg[g * 512 + t] = s / fmaxf(cnt, 1.f);
    g_xg[g * 512 + 256 + t] = s;
}

// ---------------- MLP heads ----------------
__global__ __launch_bounds__(256) void mlp_kernel(
    const float* __restrict__ pw1, const float* __restrict__ pb1,
    const float* __restrict__ pw2, const float* __restrict__ pb2,
    const float* __restrict__ pw3, const float* __restrict__ pb3,
    const float* __restrict__ mw1, const float* __restrict__ mb1,
    const float* __restrict__ mw2, const float* __restrict__ mb2,
    const float* __restrict__ mw3, const float* __restrict__ mb3,
    float* __restrict__ out) {
    int g = blockIdx.x & 15;
    int head = blockIdx.x >> 4;
    const float* w1 = head ? mw1 : pw1; const float* b1 = head ? mb1 : pb1;
    const float* w2 = head ? mw2 : pw2; const float* b2 = head ? mb2 : pb2;
    const float* w3 = head ? mw3 : pw3; const float* b3 = head ? mb3 : pb3;
    int t = threadIdx.x;
    __shared__ float sx[512];
    __shared__ float h1[256];
    __shared__ float h2[128];
    sx[t] = g_xg[g * 512 + t];
    sx[t + 256] = g_xg[g * 512 + 256 + t];
    __syncthreads();
    {
        const float* wr = w1 + (size_t)t * 512;
        float a = b1[t];
        for (int k = 0; k < 512; k++) a = fmaf(sx[k], wr[k], a);
        h1[t] = geluf(a);
    }
    __syncthreads();
    if (t < 128) {
        const float* wr = w2 + (size_t)t * 256;
        float a = b2[t];
        for (int k = 0; k < 256; k++) a = fmaf(h1[k], wr[k], a);
        h2[t] = geluf(a);
    }
    __syncthreads();
    if (t < 3) {
        const float* wr = w3 + (size_t)t * 128;
        float a = b3[t];
        for (int k = 0; k < 128; k++) a = fmaf(h2[k], wr[k], a);
        out[head * 48 + g * 3 + t] = 1.f / (1.f + expf(-a));
    }
}

// ---------------- launcher ----------------
extern "C" void kernel_launch(void* const* d_in, const int* in_sizes, int n_in,
                              void* d_out, int out_size) {
    const float* x          = (const float*)d_in[0];
    const int*   edge_index = (const int*)d_in[1];
    const float* edge_attr  = (const float*)d_in[2];
    const int*   batch      = (const int*)d_in[3];
    const float* node_w     = (const float*)d_in[4];
    const float* node_b     = (const float*)d_in[5];
    const float* eew        = (const float*)d_in[6];
    const float* eeb        = (const float*)d_in[7];
    const float* lin_w      = (const float*)d_in[8];
    const float* att_src    = (const float*)d_in[9];
    const float* att_dst    = (const float*)d_in[10];
    const float* att_edge   = (const float*)d_in[11];
    const float* lin_edge_w = (const float*)d_in[12];
    const float* conv_b     = (const float*)d_in[13];
    const float* ln_g       = (const float*)d_in[14];
    const float* ln_b       = (const float*)d_in[15];
    const float* pw1 = (const float*)d_in[16]; const float* pb1 = (const float*)d_in[17];
    const float* pw2 = (const float*)d_in[18]; const float* pb2 = (const float*)d_in[19];
    const float* pw3 = (const float*)d_in[20]; const float* pb3 = (const float*)d_in[21];
    const float* mw1 = (const float*)d_in[22]; const float* mb1 = (const float*)d_in[23];
    const float* mw2 = (const float*)d_in[24]; const float* mb2 = (const float*)d_in[25];
    const float* mw3 = (const float*)d_in[26]; const float* mb3 = (const float*)d_in[27];
    float* out = (float*)d_out;

    // setup
    zero_kernel<<<64, 256>>>();
    deg_kernel<<<(NE + 255) / 256, 256>>>(edge_index);
    scan_kernel<<<1, 1024>>>();
    fill_kernel<<<(NE + 255) / 256, 256>>>(edge_index);
    loopslot_kernel<<<(NN + 255) / 256, 256>>>();
    u_kernel<<<48, 256>>>(att_edge, lin_edge_w, eew, eeb);
    alphaP_kernel<<<(EN + 127) / 128, 128>>>(edge_attr);
    loopdiv_kernel<<<NN, 256>>>();
    bounds_kernel<<<(NN + 255) / 256, 256>>>(batch);

    float *d_h, *d_xw;
    cudaGetSymbolAddress((void**)&d_h, g_h);
    cudaGetSymbolAddress((void**)&d_xw, g_xw);

    // node embedding: h = x @ node_w^T + node_b
    {
        dim3 grid((NN + 127) / 128, 2);
        gemm_nt<<<grid, 256>>>(x, node_w, node_b, d_h, NN, 64);
    }

    for (int layer = 0; layer < NL; layer++) {
        dim3 grid((NN + 127) / 128, 2);
        gemm_nt<<<grid, 256>>>(d_h, lin_w + (size_t)layer * 65536, nullptr, d_xw, NN, 256);
        asrc_kernel<<<(NN * NHD + 255) / 256, 256>>>(layer, att_src, att_dst);
        alphaF_kernel<<<(EN + 255) / 256, 256>>>(layer);
        agg_kernel<<<NN, 256>>>(layer, conv_b, ln_g, ln_b);
    }

    pool_kernel<<<NG, 256>>>();
    mlp_kernel<<<32, 256>>>(pw1, pb1, pw2, pb2, pw3, pb3,
                            mw1, mb1, mw2, mb2, mw3, mb3, out);
}

// round 14
// speedup vs baseline: 1.8629x; 1.0638x over previous
#include <cuda_runtime.h>
#include <math.h>
#include <stdint.h>

#define NN 10000
#define NE 320000
#define EN 330000   // NE + NN self-loop slots
#define HH 256
#define NL 6
#define NHD 8
#define NG 16
#define DCAP 128    // per-warp smem alpha cache capacity

// ---------------- static device scratch ----------------
__device__ float g_h[NN * HH];
__device__ float g_xw[NN * HH];
__device__ float g_asrc[NN * NHD];
__device__ float g_adst[NN * NHD];
__device__ float g_alphaP[48 * EN];   // [layer*8+head][csr pos]
__device__ float g_alphaF[NHD * EN];  // [head][csr pos], current layer
__device__ float g_u[48 * 32];
__device__ float g_uc[48];
__device__ int   g_deg[NN];
__device__ int   g_fill[NN];
__device__ int   g_off[NN + 1];
__device__ int   g_csrc[EN];
__device__ int   g_peid[EN];
__device__ int   g_pnode[EN];
__device__ int   g_gs[NG], g_ge[NG];
__device__ float g_xg[NG * 2 * HH];   // [g][mean(256) | sum(256)]

__device__ __forceinline__ float geluf(float x) {
    return 0.5f * x * (1.0f + erff(x * 0.70710678118654752f));
}

__device__ __forceinline__ uint32_t f2tf(float f) {
    uint32_t r;
    asm("cvt.rna.tf32.f32 %0, %1;" : "=r"(r) : "f"(f));
    return r;
}

// ---------------- zero accumulators ----------------
__global__ void zero_kernel() {
    int i = blockIdx.x * blockDim.x + threadIdx.x;
    int stride = gridDim.x * blockDim.x;
    for (int j = i; j < NN; j += stride) { g_deg[j] = 0; g_fill[j] = 0; }
    if (i < NG) { g_gs[i] = 0; g_ge[i] = 0; }
}

// ---------------- CSR build (by destination) ----------------
__global__ void deg_kernel(const int* __restrict__ ei) {
    int e = blockIdx.x * blockDim.x + threadIdx.x;
    if (e < NE) atomicAdd(&g_deg[ei[NE + e]], 1);
}

__global__ void scan_kernel() {
    __shared__ int s[1024];
    int t = threadIdx.x;
    int d[10];
    int loc = 0;
#pragma unroll
    for (int j = 0; j < 10; j++) {
        int n = t * 10 + j;
        int v = (n < NN) ? (g_deg[n] + 1) : 0;   // +1 self-loop slot
        d[j] = v; loc += v;
    }
    s[t] = loc; __syncthreads();
    for (int off = 1; off < 1024; off <<= 1) {
        int v = (t >= off) ? s[t - off] : 0;
        __syncthreads();
        s[t] += v;
        __syncthreads();
    }
    int ex = s[t] - loc;
#pragma unroll
    for (int j = 0; j < 10; j++) {
        int n = t * 10 + j;
        if (n < NN) g_off[n] = ex;
        ex += d[j];
    }
    if (t == 1023) g_off[NN] = s[1023];
}

__global__ void fill_kernel(const int* __restrict__ ei) {
    int e = blockIdx.x * blockDim.x + threadIdx.x;
    if (e >= NE) return;
    int d = ei[NE + e];
    int pos = g_off[d] + atomicAdd(&g_fill[d], 1);
    g_csrc[pos] = ei[e];
    g_peid[pos] = e;
    g_pnode[pos] = d;
}

__global__ void loopslot_kernel() {
    int n = blockIdx.x * blockDim.x + threadIdx.x;
    if (n >= NN) return;
    int pos = g_off[n + 1] - 1;
    g_csrc[pos] = n;
    g_peid[pos] = NE + n;
    g_pnode[pos] = n;
}

// ------- contracted edge weights: u[i,h,f] = ((att_edge slice @ lin_edge_w slice) @ eew) -------
__global__ void u_kernel(const float* __restrict__ att_edge,
                         const float* __restrict__ lin_edge_w,
                         const float* __restrict__ eew,
                         const float* __restrict__ eeb) {
    int comb = blockIdx.x;          // layer*8 + head
    int i = comb >> 3, hd = comb & 7;
    int tid = threadIdx.x;          // 256 threads
    __shared__ float sae[32];
    __shared__ float sv[256];
    if (tid < 32) sae[tid] = att_edge[i * 256 + hd * 32 + tid];
    __syncthreads();
    const float* lw = lin_edge_w + (size_t)i * 65536 + (size_t)(hd * 32) * 256 + tid;
    float v = 0.f;
#pragma unroll
    for (int o = 0; o < 32; o++) v = fmaf(sae[o], lw[(size_t)o * 256], v);
    sv[tid] = v; __syncthreads();
    if (tid < 32) {
        float u = 0.f;
        for (int c = 0; c < 256; c++) u = fmaf(sv[c], eew[c * 32 + tid], u);
        g_u[comb * 32 + tid] = u;
    }
    if (tid == 255) {
        float s = 0.f;
        for (int c = 0; c < 256; c++) s = fmaf(sv[c], eeb[c], s);
        g_uc[comb] = s;
    }
}

// ------- per-edge attr attention term for all 48 (layer,head) in CSR order -------
__global__ __launch_bounds__(128) void alphaP_kernel(const float* __restrict__ edge_attr) {
    __shared__ float su[48 * 32];
    __shared__ float suc[48];
    int tid = threadIdx.x;
    for (int j = tid; j < 48 * 32; j += 128) su[j] = g_u[j];
    if (tid < 48) suc[tid] = g_uc[tid];
    __syncthreads();
    int pos = blockIdx.x * 128 + tid;
    if (pos >= EN) return;
    int e = g_peid[pos];
    if (e >= NE) return;          // self-loop slot written by loopdiv_kernel
    float ea[32];
    const float4* p = (const float4*)(edge_attr + (size_t)e * 32);
#pragma unroll
    for (int q = 0; q < 8; q++) {
        float4 v = p[q];
        ea[4 * q] = v.x; ea[4 * q + 1] = v.y; ea[4 * q + 2] = v.z; ea[4 * q + 3] = v.w;
    }
#pragma unroll 2
    for (int c = 0; c < 48; c++) {
        const float4* u4 = (const float4*)&su[c * 32];
        float a0 = suc[c], a1 = 0.f, a2 = 0.f, a3 = 0.f;
#pragma unroll
        for (int q = 0; q < 8; q++) {
            float4 uu = u4[q];
            a0 = fmaf(ea[4 * q], uu.x, a0);
            a1 = fmaf(ea[4 * q + 1], uu.y, a1);
            a2 = fmaf(ea[4 * q + 2], uu.z, a2);
            a3 = fmaf(ea[4 * q + 3], uu.w, a3);
        }
        g_alphaP[(size_t)c * EN + pos] = (a0 + a1) + (a2 + a3);
    }
}

// ------- self-loop 'mean' slot: segment mean of alphaP over incoming edges (no atomics) -------
__global__ __launch_bounds__(256) void loopdiv_kernel() {
    int n = blockIdx.x;
    int wid = threadIdx.x >> 5, lane = threadIdx.x & 31;
    int beg = g_off[n], last = g_off[n + 1] - 1;   // [beg,last) are real edges
    float invc = 1.f / fmaxf((float)(last - beg), 1.f);
    for (int c = wid; c < 48; c += 8) {
        const float* ap = g_alphaP + (size_t)c * EN;
        float s = 0.f;
        for (int j = beg + lane; j < last; j += 32) s += ap[j];
#pragma unroll
        for (int o = 16; o > 0; o >>= 1) s += __shfl_xor_sync(0xffffffffu, s, o);
        if (lane == 0) g_alphaP[(size_t)c * EN + last] = s * invc;
    }
}

// ---------------- tf32 tensor-core GEMM: C[M,256] = A[M,K] @ B[256,K]^T (+bias) ----------------
__global__ __launch_bounds__(256) void gemm_nt(const float* __restrict__ A,
                                               const float* __restrict__ B,
                                               const float* __restrict__ bias,
                                               float* __restrict__ C,
                                               int M, int K) {
    __shared__ uint32_t As2[128 * 36];
    __shared__ uint32_t Bs2[128 * 36];
    int mBase = blockIdx.x * 128, nBase = blockIdx.y * 128;
    int tid = threadIdx.x;
    int warpId = tid >> 5, lane = tid & 31;
    int wm = warpId & 1, wn = warpId >> 1;        // 2 x 4 warp grid
    int g = lane >> 2, tig = lane & 3;

    float c[4][4][4];                              // [mt][nt][frag]
#pragma unroll
    for (int mt = 0; mt < 4; mt++)
#pragma unroll
        for (int nt = 0; nt < 4; nt++)
#pragma unroll
            for (int q = 0; q < 4; q++) c[mt][nt][q] = 0.f;

    for (int kb = 0; kb < K; kb += 32) {
#pragma unroll
        for (int i = 0; i < 4; i++) {
            int id = tid + i * 256;
            int row = id >> 3;
            int kc = (id & 7) << 2;
            float4 v = make_float4(0.f, 0.f, 0.f, 0.f);
            int gm = mBase + row;
            if (gm < M) v = *(const float4*)(A + (size_t)gm * K + kb + kc);
            uint4 t = make_uint4(f2tf(v.x), f2tf(v.y), f2tf(v.z), f2tf(v.w));
            *(uint4*)&As2[row * 36 + kc] = t;
        }
#pragma unroll
        for (int i = 0; i < 4; i++) {
            int id = tid + i * 256;
            int row = id >> 3;
            int kc = (id & 7) << 2;
            float4 v = *(const float4*)(B + (size_t)(nBase + row) * K + kb + kc);
            uint4 t = make_uint4(f2tf(v.x), f2tf(v.y), f2tf(v.z), f2tf(v.w));
            *(uint4*)&Bs2[row * 36 + kc] = t;
        }
        __syncthreads();

#pragma unroll
        for (int k8 = 0; k8 < 4; k8++) {
            int k0 = k8 * 8;
            uint32_t a[4][4], b[4][2];
#pragma unroll
            for (int mt = 0; mt < 4; mt++) {
                int r0 = (wm * 64 + mt * 16 + g) * 36;
                int r1 = (wm * 64 + mt * 16 + 8 + g) * 36;
                a[mt][0] = As2[r0 + k0 + tig];
                a[mt][1] = As2[r1 + k0 + tig];
                a[mt][2] = As2[r0 + k0 + tig + 4];
                a[mt][3] = As2[r1 + k0 + tig + 4];
            }
#pragma unroll
            for (int nt = 0; nt < 4; nt++) {
                int rn = (wn * 32 + nt * 8 + g) * 36;
                b[nt][0] = Bs2[rn + k0 + tig];
                b[nt][1] = Bs2[rn + k0 + tig + 4];
            }
#pragma unroll
            for (int mt = 0; mt < 4; mt++)
#pragma unroll
                for (int nt = 0; nt < 4; nt++) {
                    asm volatile(
                        "mma.sync.aligned.m16n8k8.row.col.f32.tf32.tf32.f32 "
                        "{%0,%1,%2,%3}, {%4,%5,%6,%7}, {%8,%9}, {%0,%1,%2,%3};"
                        : "+f"(c[mt][nt][0]), "+f"(c[mt][nt][1]),
                          "+f"(c[mt][nt][2]), "+f"(c[mt][nt][3])
                        : "r"(a[mt][0]), "r"(a[mt][1]), "r"(a[mt][2]), "r"(a[mt][3]),
                          "r"(b[nt][0]), "r"(b[nt][1]));
                }
        }
        __syncthreads();
    }

#pragma unroll
    for (int mt = 0; mt < 4; mt++) {
        int r0 = mBase + wm * 64 + mt * 16 + g;
        int r1 = r0 + 8;
#pragma unroll
        for (int nt = 0; nt < 4; nt++) {
            int cn = nBase + wn * 32 + nt * 8 + 2 * tig;
            float b0 = 0.f, b1 = 0.f;
            if (bias) { b0 = bias[cn]; b1 = bias[cn + 1]; }
            if (r0 < M) {
                float2 v = make_float2(c[mt][nt][0] + b0, c[mt][nt][1] + b1);
                *(float2*)(C + (size_t)r0 * HH + cn) = v;
            }
            if (r1 < M) {
                float2 v = make_float2(c[mt][nt][2] + b0, c[mt][nt][3] + b1);
                *(float2*)(C + (size_t)r1 * HH + cn) = v;
            }
        }
    }
}

// ---------------- per-node attention scalars ----------------
__global__ void asrc_kernel(int layer,
                            const float* __restrict__ attS,
                            const float* __restrict__ attD) {
    int idx = blockIdx.x * blockDim.x + threadIdx.x;
    if (idx >= NN * NHD) return;
    int n = idx >> 3, hd = idx & 7;
    const float* xr = g_xw + (size_t)n * HH + hd * 32;
    const float* aS = attS + layer * 256 + hd * 32;
    const float* aD = attD + layer * 256 + hd * 32;
    float s = 0.f, d = 0.f;
#pragma unroll
    for (int o = 0; o < 32; o++) {
        float xv = xr[o];
        s = fmaf(xv, aS[o], s);
        d = fmaf(xv, aD[o], d);
    }
    g_asrc[idx] = s;
    g_adst[idx] = d;
}

// ---------------- full leaky-relu'd alpha per CSR slot ----------------
__global__ void alphaF_kernel(int layer) {
    int pos = blockIdx.x * blockDim.x + threadIdx.x;
    if (pos >= EN) return;
    int src = g_csrc[pos];
    int nd  = g_pnode[pos];
    const float4* sa = (const float4*)(g_asrc + (size_t)src * 8);
    const float4* da = (const float4*)(g_adst + (size_t)nd * 8);
    float4 s0 = sa[0], s1 = sa[1], d0 = da[0], d1 = da[1];
    float as[8] = {s0.x, s0.y, s0.z, s0.w, s1.x, s1.y, s1.z, s1.w};
    float ad[8] = {d0.x, d0.y, d0.z, d0.w, d1.x, d1.y, d1.z, d1.w};
#pragma unroll
    for (int hd = 0; hd < 8; hd++) {
        float a = as[hd] + ad[hd] + g_alphaP[(size_t)(layer * 8 + hd) * EN + pos];
        a = a > 0.f ? a : 0.2f * a;
        g_alphaF[(size_t)hd * EN + pos] = a;
    }
}

// --------- fused softmax + aggregate + bias + LayerNorm + GELU + residual ---------
// pass1: coalesced per-head alphaF read -> smem cache + segment max; warp0 caches csrc.
// pass2: serial gather fully from smem (exp + denom fused); global only for xw gather.
__global__ __launch_bounds__(256) void agg_kernel(int layer,
                                                  const float* __restrict__ convb,
                                                  const float* __restrict__ lng,
                                                  const float* __restrict__ lnb) {
    __shared__ float sbuf[NHD][DCAP];
    __shared__ int   s_src[DCAP];
    __shared__ float red[256];
    int n = blockIdx.x, tid = threadIdx.x;
    int hd = tid >> 5, lane = tid & 31;
    int beg = g_off[n], end = g_off[n + 1];
    int deg = end - beg;
    const float* aF = g_alphaF + (size_t)hd * EN;

    // pass 1: segment max + smem caching (coalesced reads only)
    float m = -3.0e38f;
    for (int j = beg + lane; j < end; j += 32) {
        float a = aF[j];
        int o = j - beg;
        if (o < DCAP) {
            sbuf[hd][o] = a;
            if (hd == 0) s_src[o] = g_csrc[j];
        }
        m = fmaxf(m, a);
    }
#pragma unroll
    for (int o = 16; o > 0; o >>= 1) m = fmaxf(m, __shfl_xor_sync(0xffffffffu, m, o));
    __syncthreads();

    // pass 2: fused denominator + gather (unnormalized), fast exp
    float s = 0.f, acc = 0.f;
    const float* xwp = g_xw + hd * 32 + lane;
    if (deg <= DCAP) {
        for (int o = 0; o < deg; o++) {
            float e = __expf(sbuf[hd][o] - m);
            int src = s_src[o];
            s += e;
            acc = fmaf(e, xwp[(size_t)src * HH], acc);
        }
    } else {
        for (int j = beg; j < end; j++) {
            float e = __expf(aF[j] - m);
            int src = g_csrc[j];
            s += e;
            acc = fmaf(e, xwp[(size_t)src * HH], acc);
        }
    }
    acc *= 1.f / (s + 1e-16f);

    float v = acc + convb[layer * HH + tid];
    red[tid] = v; __syncthreads();
#pragma unroll
    for (int st = 128; st > 0; st >>= 1) {
        if (tid < st) red[tid] += red[tid + st];
        __syncthreads();
    }
    float mu = red[0] * (1.f / 256.f);
    __syncthreads();
    float dv = v - mu;
    red[tid] = dv * dv; __syncthreads();
#pragma unroll
    for (int st = 128; st > 0; st >>= 1) {
        if (tid < st) red[tid] += red[tid + st];
        __syncthreads();
    }
    float var = red[0] * (1.f / 256.f);
    float y = lng[layer * HH + tid] * dv * rsqrtf(var + 1e-5f) + lnb[layer * HH + tid];
    float gv = geluf(y);
    float hn = (layer > 0) ? (gv + g_h[(size_t)n * HH + tid]) : gv;
    g_h[(size_t)n * HH + tid] = hn;
}

// ---------------- graph pooling (sorted batch -> ranges, no atomics) ----------------
__global__ void bounds_kernel(const int* __restrict__ batch) {
    int n = blockIdx.x * blockDim.x + threadIdx.x;
    if (n >= NN) return;
    int b = batch[n];
    if (n == 0 || batch[n - 1] != b) g_gs[b] = n;
    if (n == NN - 1 || batch[n + 1] != b) g_ge[b] = n + 1;
}

__global__ __launch_bounds__(256) void pool_kernel() {
    int g = blockIdx.x, t = threadIdx.x;
    int beg = g_gs[g], end = g_ge[g];
    float s = 0.f;
    for (int n = beg; n < end; n++) s += g_h[(size_t)n * HH + t];
    float cnt = (float)(end - beg);
    g_xg[g * 512 + t] = s / fmaxf(cnt, 1.f);
    g_xg[g * 512 + 256 + t] = s;
}

// ---------------- MLP heads ----------------
__global__ __launch_bounds__(256) void mlp_kernel(
    const float* __restrict__ pw1, const float* __restrict__ pb1,
    const float* __restrict__ pw2, const float* __restrict__ pb2,
    const float* __restrict__ pw3, const float* __restrict__ pb3,
    const float* __restrict__ mw1, const float* __restrict__ mb1,
    const float* __restrict__ mw2, const float* __restrict__ mb2,
    const float* __restrict__ mw3, const float* __restrict__ mb3,
    float* __restrict__ out) {
    int g = blockIdx.x & 15;
    int head = blockIdx.x >> 4;
    const float* w1 = head ? mw1 : pw1; const float* b1 = head ? mb1 : pb1;
    const float* w2 = head ? mw2 : pw2; const float* b2 = head ? mb2 : pb2;
    const float* w3 = head ? mw3 : pw3; const float* b3 = head ? mb3 : pb3;
    int t = threadIdx.x;
    __shared__ float sx[512];
    __shared__ float h1[256];
    __shared__ float h2[128];
    sx[t] = g_xg[g * 512 + t];
    sx[t + 256] = g_xg[g * 512 + 256 + t];
    __syncthreads();
    {
        const float* wr = w1 + (size_t)t * 512;
        float a = b1[t];
        for (int k = 0; k < 512; k++) a = fmaf(sx[k], wr[k], a);
        h1[t] = geluf(a);
    }
    __syncthreads();
    if (t < 128) {
        const float* wr = w2 + (size_t)t * 256;
        float a = b2[t];
        for (int k = 0; k < 256; k++) a = fmaf(h1[k], wr[k], a);
        h2[t] = geluf(a);
    }
    __syncthreads();
    if (t < 3) {
        const float* wr = w3 + (size_t)t * 128;
        float a = b3[t];
        for (int k = 0; k < 128; k++) a = fmaf(h2[k], wr[k], a);
        out[head * 48 + g * 3 + t] = 1.f / (1.f + expf(-a));
    }
}

// ---------------- launcher ----------------
extern "C" void kernel_launch(void* const* d_in, const int* in_sizes, int n_in,
                              void* d_out, int out_size) {
    const float* x          = (const float*)d_in[0];
    const int*   edge_index = (const int*)d_in[1];
    const float* edge_attr  = (const float*)d_in[2];
    const int*   batch      = (const int*)d_in[3];
    const float* node_w     = (const float*)d_in[4];
    const float* node_b     = (const float*)d_in[5];
    const float* eew        = (const float*)d_in[6];
    const float* eeb        = (const float*)d_in[7];
    const float* lin_w      = (const float*)d_in[8];
    const float* att_src    = (const float*)d_in[9];
    const float* att_dst    = (const float*)d_in[10];
    const float* att_edge   = (const float*)d_in[11];
    const float* lin_edge_w = (const float*)d_in[12];
    const float* conv_b     = (const float*)d_in[13];
    const float* ln_g       = (const float*)d_in[14];
    const float* ln_b       = (const float*)d_in[15];
    const float* pw1 = (const float*)d_in[16]; const float* pb1 = (const float*)d_in[17];
    const float* pw2 = (const float*)d_in[18]; const float* pb2 = (const float*)d_in[19];
    const float* pw3 = (const float*)d_in[20]; const float* pb3 = (const float*)d_in[21];
    const float* mw1 = (const float*)d_in[22]; const float* mb1 = (const float*)d_in[23];
    const float* mw2 = (const float*)d_in[24]; const float* mb2 = (const float*)d_in[25];
    const float* mw3 = (const float*)d_in[26]; const float* mb3 = (const float*)d_in[27];
    float* out = (float*)d_out;

    // setup
    zero_kernel<<<64, 256>>>();
    deg_kernel<<<(NE + 255) / 256, 256>>>(edge_index);
    scan_kernel<<<1, 1024>>>();
    fill_kernel<<<(NE + 255) / 256, 256>>>(edge_index);
    loopslot_kernel<<<(NN + 255) / 256, 256>>>();
    u_kernel<<<48, 256>>>(att_edge, lin_edge_w, eew, eeb);
    alphaP_kernel<<<(EN + 127) / 128, 128>>>(edge_attr);
    loopdiv_kernel<<<NN, 256>>>();
    bounds_kernel<<<(NN + 255) / 256, 256>>>(batch);

    float *d_h, *d_xw;
    cudaGetSymbolAddress((void**)&d_h, g_h);
    cudaGetSymbolAddress((void**)&d_xw, g_xw);

    // node embedding: h = x @ node_w^T + node_b
    {
        dim3 grid((NN + 127) / 128, 2);
        gemm_nt<<<grid, 256>>>(x, node_w, node_b, d_h, NN, 64);
    }

    for (int layer = 0; layer < NL; layer++) {
        dim3 grid((NN + 127) / 128, 2);
        gemm_nt<<<grid, 256>>>(d_h, lin_w + (size_t)layer * 65536, nullptr, d_xw, NN, 256);
        asrc_kernel<<<(NN * NHD + 255) / 256, 256>>>(layer, att_src, att_dst);
        alphaF_kernel<<<(EN + 255) / 256, 256>>>(layer);
        agg_kernel<<<NN, 256>>>(layer, conv_b, ln_g, ln_b);
    }

    pool_kernel<<<NG, 256>>>();
    mlp_kernel<<<32, 256>>>(pw1, pb1, pw2, pb2, pw3, pb3,
                            mw1, mb1, mw2, mb2, mw3, mb3, out);
}

// round 15
// speedup vs baseline: 1.9269x; 1.0344x over previous
#include <cuda_runtime.h>
#include <math.h>
#include <stdint.h>

#define NN 10000
#define NE 320000
#define EN 330000   // NE + NN self-loop slots
#define HH 256
#define NL 6
#define NHD 8
#define NG 16
#define DCAP 128    // per-warp smem alpha cache capacity

// ---------------- static device scratch ----------------
__device__ float g_h[NN * HH];
__device__ float g_xw[NN * HH];
__device__ float g_asrc[NN * NHD];
__device__ float g_adst[NN * NHD];
__device__ float g_alphaP[48 * EN];   // [layer*8+head][csr pos]
__device__ float g_u[48 * 32];
__device__ float g_uc[48];
__device__ int   g_deg[NN];
__device__ int   g_fill[NN];
__device__ int   g_off[NN + 1];
__device__ int   g_csrc[EN];
__device__ int   g_peid[EN];
__device__ int   g_gs[NG], g_ge[NG];
__device__ float g_xg[NG * 2 * HH];   // [g][mean(256) | sum(256)]

__device__ __forceinline__ float geluf(float x) {
    return 0.5f * x * (1.0f + erff(x * 0.70710678118654752f));
}

__device__ __forceinline__ uint32_t f2tf(float f) {
    uint32_t r;
    asm("cvt.rna.tf32.f32 %0, %1;" : "=r"(r) : "f"(f));
    return r;
}

// ---------------- zero accumulators ----------------
__global__ void zero_kernel() {
    int i = blockIdx.x * blockDim.x + threadIdx.x;
    int stride = gridDim.x * blockDim.x;
    for (int j = i; j < NN; j += stride) { g_deg[j] = 0; g_fill[j] = 0; }
    if (i < NG) { g_gs[i] = 0; g_ge[i] = 0; }
}

// ---------------- CSR build (by destination) ----------------
__global__ void deg_kernel(const int* __restrict__ ei) {
    int e = blockIdx.x * blockDim.x + threadIdx.x;
    if (e < NE) atomicAdd(&g_deg[ei[NE + e]], 1);
}

__global__ void scan_kernel() {
    __shared__ int s[1024];
    int t = threadIdx.x;
    int d[10];
    int loc = 0;
#pragma unroll
    for (int j = 0; j < 10; j++) {
        int n = t * 10 + j;
        int v = (n < NN) ? (g_deg[n] + 1) : 0;   // +1 self-loop slot
        d[j] = v; loc += v;
    }
    s[t] = loc; __syncthreads();
    for (int off = 1; off < 1024; off <<= 1) {
        int v = (t >= off) ? s[t - off] : 0;
        __syncthreads();
        s[t] += v;
        __syncthreads();
    }
    int ex = s[t] - loc;
#pragma unroll
    for (int j = 0; j < 10; j++) {
        int n = t * 10 + j;
        if (n < NN) g_off[n] = ex;
        ex += d[j];
    }
    if (t == 1023) g_off[NN] = s[1023];
}

__global__ void fill_kernel(const int* __restrict__ ei) {
    int e = blockIdx.x * blockDim.x + threadIdx.x;
    if (e >= NE) return;
    int d = ei[NE + e];
    int pos = g_off[d] + atomicAdd(&g_fill[d], 1);
    g_csrc[pos] = ei[e];
    g_peid[pos] = e;
}

__global__ void loopslot_kernel() {
    int n = blockIdx.x * blockDim.x + threadIdx.x;
    if (n >= NN) return;
    int pos = g_off[n + 1] - 1;
    g_csrc[pos] = n;
    g_peid[pos] = NE + n;
}

// ------- contracted edge weights: u[i,h,f] = ((att_edge slice @ lin_edge_w slice) @ eew) -------
__global__ void u_kernel(const float* __restrict__ att_edge,
                         const float* __restrict__ lin_edge_w,
                         const float* __restrict__ eew,
                         const float* __restrict__ eeb) {
    int comb = blockIdx.x;          // layer*8 + head
    int i = comb >> 3, hd = comb & 7;
    int tid = threadIdx.x;          // 256 threads
    __shared__ float sae[32];
    __shared__ float sv[256];
    if (tid < 32) sae[tid] = att_edge[i * 256 + hd * 32 + tid];
    __syncthreads();
    const float* lw = lin_edge_w + (size_t)i * 65536 + (size_t)(hd * 32) * 256 + tid;
    float v = 0.f;
#pragma unroll
    for (int o = 0; o < 32; o++) v = fmaf(sae[o], lw[(size_t)o * 256], v);
    sv[tid] = v; __syncthreads();
    if (tid < 32) {
        float u = 0.f;
        for (int c = 0; c < 256; c++) u = fmaf(sv[c], eew[c * 32 + tid], u);
        g_u[comb * 32 + tid] = u;
    }
    if (tid == 255) {
        float s = 0.f;
        for (int c = 0; c < 256; c++) s = fmaf(sv[c], eeb[c], s);
        g_uc[comb] = s;
    }
}

// ------- per-edge attr attention term for all 48 (layer,head) in CSR order -------
__global__ __launch_bounds__(128) void alphaP_kernel(const float* __restrict__ edge_attr) {
    __shared__ float su[48 * 32];
    __shared__ float suc[48];
    int tid = threadIdx.x;
    for (int j = tid; j < 48 * 32; j += 128) su[j] = g_u[j];
    if (tid < 48) suc[tid] = g_uc[tid];
    __syncthreads();
    int pos = blockIdx.x * 128 + tid;
    if (pos >= EN) return;
    int e = g_peid[pos];
    if (e >= NE) return;          // self-loop slot written by loopdiv_kernel
    float ea[32];
    const float4* p = (const float4*)(edge_attr + (size_t)e * 32);
#pragma unroll
    for (int q = 0; q < 8; q++) {
        float4 v = p[q];
        ea[4 * q] = v.x; ea[4 * q + 1] = v.y; ea[4 * q + 2] = v.z; ea[4 * q + 3] = v.w;
    }
#pragma unroll 2
    for (int c = 0; c < 48; c++) {
        const float4* u4 = (const float4*)&su[c * 32];
        float a0 = suc[c], a1 = 0.f, a2 = 0.f, a3 = 0.f;
#pragma unroll
        for (int q = 0; q < 8; q++) {
            float4 uu = u4[q];
            a0 = fmaf(ea[4 * q], uu.x, a0);
            a1 = fmaf(ea[4 * q + 1], uu.y, a1);
            a2 = fmaf(ea[4 * q + 2], uu.z, a2);
            a3 = fmaf(ea[4 * q + 3], uu.w, a3);
        }
        g_alphaP[(size_t)c * EN + pos] = (a0 + a1) + (a2 + a3);
    }
}

// ------- self-loop 'mean' slot: segment mean of alphaP over incoming edges (no atomics) -------
__global__ __launch_bounds__(256) void loopdiv_kernel() {
    int n = blockIdx.x;
    int wid = threadIdx.x >> 5, lane = threadIdx.x & 31;
    int beg = g_off[n], last = g_off[n + 1] - 1;   // [beg,last) are real edges
    float invc = 1.f / fmaxf((float)(last - beg), 1.f);
    for (int c = wid; c < 48; c += 8) {
        const float* ap = g_alphaP + (size_t)c * EN;
        float s = 0.f;
        for (int j = beg + lane; j < last; j += 32) s += ap[j];
#pragma unroll
        for (int o = 16; o > 0; o >>= 1) s += __shfl_xor_sync(0xffffffffu, s, o);
        if (lane == 0) g_alphaP[(size_t)c * EN + last] = s * invc;
    }
}

// ---------------- tf32 tensor-core GEMM: C[M,256] = A[M,K] @ B[256,K]^T (+bias) ----------------
__global__ __launch_bounds__(256) void gemm_nt(const float* __restrict__ A,
                                               const float* __restrict__ B,
                                               const float* __restrict__ bias,
                                               float* __restrict__ C,
                                               int M, int K) {
    __shared__ uint32_t As2[128 * 36];
    __shared__ uint32_t Bs2[128 * 36];
    int mBase = blockIdx.x * 128, nBase = blockIdx.y * 128;
    int tid = threadIdx.x;
    int warpId = tid >> 5, lane = tid & 31;
    int wm = warpId & 1, wn = warpId >> 1;        // 2 x 4 warp grid
    int g = lane >> 2, tig = lane & 3;

    float c[4][4][4];                              // [mt][nt][frag]
#pragma unroll
    for (int mt = 0; mt < 4; mt++)
#pragma unroll
        for (int nt = 0; nt < 4; nt++)
#pragma unroll
            for (int q = 0; q < 4; q++) c[mt][nt][q] = 0.f;

    for (int kb = 0; kb < K; kb += 32) {
#pragma unroll
        for (int i = 0; i < 4; i++) {
            int id = tid + i * 256;
            int row = id >> 3;
            int kc = (id & 7) << 2;
            float4 v = make_float4(0.f, 0.f, 0.f, 0.f);
            int gm = mBase + row;
            if (gm < M) v = *(const float4*)(A + (size_t)gm * K + kb + kc);
            uint4 t = make_uint4(f2tf(v.x), f2tf(v.y), f2tf(v.z), f2tf(v.w));
            *(uint4*)&As2[row * 36 + kc] = t;
        }
#pragma unroll
        for (int i = 0; i < 4; i++) {
            int id = tid + i * 256;
            int row = id >> 3;
            int kc = (id & 7) << 2;
            float4 v = *(const float4*)(B + (size_t)(nBase + row) * K + kb + kc);
            uint4 t = make_uint4(f2tf(v.x), f2tf(v.y), f2tf(v.z), f2tf(v.w));
            *(uint4*)&Bs2[row * 36 + kc] = t;
        }
        __syncthreads();

#pragma unroll
        for (int k8 = 0; k8 < 4; k8++) {
            int k0 = k8 * 8;
            uint32_t a[4][4], b[4][2];
#pragma unroll
            for (int mt = 0; mt < 4; mt++) {
                int r0 = (wm * 64 + mt * 16 + g) * 36;
                int r1 = (wm * 64 + mt * 16 + 8 + g) * 36;
                a[mt][0] = As2[r0 + k0 + tig];
                a[mt][1] = As2[r1 + k0 + tig];
                a[mt][2] = As2[r0 + k0 + tig + 4];
                a[mt][3] = As2[r1 + k0 + tig + 4];
            }
#pragma unroll
            for (int nt = 0; nt < 4; nt++) {
                int rn = (wn * 32 + nt * 8 + g) * 36;
                b[nt][0] = Bs2[rn + k0 + tig];
                b[nt][1] = Bs2[rn + k0 + tig + 4];
            }
#pragma unroll
            for (int mt = 0; mt < 4; mt++)
#pragma unroll
                for (int nt = 0; nt < 4; nt++) {
                    asm volatile(
                        "mma.sync.aligned.m16n8k8.row.col.f32.tf32.tf32.f32 "
                        "{%0,%1,%2,%3}, {%4,%5,%6,%7}, {%8,%9}, {%0,%1,%2,%3};"
                        : "+f"(c[mt][nt][0]), "+f"(c[mt][nt][1]),
                          "+f"(c[mt][nt][2]), "+f"(c[mt][nt][3])
                        : "r"(a[mt][0]), "r"(a[mt][1]), "r"(a[mt][2]), "r"(a[mt][3]),
                          "r"(b[nt][0]), "r"(b[nt][1]));
                }
        }
        __syncthreads();
    }

#pragma unroll
    for (int mt = 0; mt < 4; mt++) {
        int r0 = mBase + wm * 64 + mt * 16 + g;
        int r1 = r0 + 8;
#pragma unroll
        for (int nt = 0; nt < 4; nt++) {
            int cn = nBase + wn * 32 + nt * 8 + 2 * tig;
            float b0 = 0.f, b1 = 0.f;
            if (bias) { b0 = bias[cn]; b1 = bias[cn + 1]; }
            if (r0 < M) {
                float2 v = make_float2(c[mt][nt][0] + b0, c[mt][nt][1] + b1);
                *(float2*)(C + (size_t)r0 * HH + cn) = v;
            }
            if (r1 < M) {
                float2 v = make_float2(c[mt][nt][2] + b0, c[mt][nt][3] + b1);
                *(float2*)(C + (size_t)r1 * HH + cn) = v;
            }
        }
    }
}

// ---------------- per-node attention scalars ----------------
__global__ void asrc_kernel(int layer,
                            const float* __restrict__ attS,
                            const float* __restrict__ attD) {
    int idx = blockIdx.x * blockDim.x + threadIdx.x;
    if (idx >= NN * NHD) return;
    int n = idx >> 3, hd = idx & 7;
    const float* xr = g_xw + (size_t)n * HH + hd * 32;
    const float* aS = attS + layer * 256 + hd * 32;
    const float* aD = attD + layer * 256 + hd * 32;
    float s = 0.f, d = 0.f;
#pragma unroll
    for (int o = 0; o < 32; o++) {
        float xv = xr[o];
        s = fmaf(xv, aS[o], s);
        d = fmaf(xv, aD[o], d);
    }
    g_asrc[idx] = s;
    g_adst[idx] = d;
}

// --------- fused alpha + softmax + aggregate + bias + LayerNorm + GELU + residual ---------
// phaseA (slot-parallel, deg<=DCAP): thread per slot computes all 8 head alphas
//   (vector asrc gather, coalesced csrc/alphaP, uniform adst) -> smem.
// then per-head max from smem; phaseB serial gather from smem (exp+denom fused).
// deg>DCAP fallback: per-head on-the-fly recompute (rare).
__global__ __launch_bounds__(256) void agg_kernel(int layer,
                                                  const float* __restrict__ convb,
                                                  const float* __restrict__ lng,
                                                  const float* __restrict__ lnb) {
    __shared__ float sbuf[NHD][DCAP];
    __shared__ int   s_src[DCAP];
    __shared__ float red[256];
    int n = blockIdx.x, tid = threadIdx.x;
    int hd = tid >> 5, lane = tid & 31;
    int beg = g_off[n], end = g_off[n + 1];
    int deg = end - beg;

    float s = 0.f, acc = 0.f;
    const float* xwp = g_xw + hd * 32 + lane;

    if (deg <= DCAP) {
        // phase A: slot-parallel alpha for all heads
        if (tid < deg) {
            int j = beg + tid;
            int src = g_csrc[j];
            s_src[tid] = src;
            const float4* sa = (const float4*)(g_asrc + (size_t)src * 8);
            const float4* da = (const float4*)(g_adst + (size_t)n * 8);
            float4 s0 = sa[0], s1 = sa[1], d0 = da[0], d1 = da[1];
            float as[8] = {s0.x, s0.y, s0.z, s0.w, s1.x, s1.y, s1.z, s1.w};
            float ad[8] = {d0.x, d0.y, d0.z, d0.w, d1.x, d1.y, d1.z, d1.w};
#pragma unroll
            for (int h = 0; h < 8; h++) {
                float a = as[h] + ad[h] + g_alphaP[(size_t)(layer * 8 + h) * EN + j];
                a = a > 0.f ? a : 0.2f * a;
                sbuf[h][tid] = a;
            }
        }
        __syncthreads();

        // per-head segment max from smem
        float m = -3.0e38f;
        for (int o = lane; o < deg; o += 32) m = fmaxf(m, sbuf[hd][o]);
#pragma unroll
        for (int o = 16; o > 0; o >>= 1) m = fmaxf(m, __shfl_xor_sync(0xffffffffu, m, o));

        // phase B: fused denominator + gather (unnormalized), fast exp
        for (int o = 0; o < deg; o++) {
            float e = __expf(sbuf[hd][o] - m);
            int src = s_src[o];
            s += e;
            acc = fmaf(e, xwp[(size_t)src * HH], acc);
        }
    } else {
        // rare fallback: per-head on-the-fly (deg > DCAP)
        const float* aP = g_alphaP + (size_t)(layer * 8 + hd) * EN;
        float adst = g_adst[n * NHD + hd];
        float m = -3.0e38f;
        for (int j = beg + lane; j < end; j += 32) {
            float a = g_asrc[(size_t)g_csrc[j] * NHD + hd] + adst + aP[j];
            a = a > 0.f ? a : 0.2f * a;
            m = fmaxf(m, a);
        }
#pragma unroll
        for (int o = 16; o > 0; o >>= 1) m = fmaxf(m, __shfl_xor_sync(0xffffffffu, m, o));
        for (int j = beg; j < end; j++) {
            int src = g_csrc[j];
            float a = g_asrc[(size_t)src * NHD + hd] + adst + aP[j];
            a = a > 0.f ? a : 0.2f * a;
            float e = __expf(a - m);
            s += e;
            acc = fmaf(e, xwp[(size_t)src * HH], acc);
        }
    }
    acc *= 1.f / (s + 1e-16f);

    float v = acc + convb[layer * HH + tid];
    red[tid] = v; __syncthreads();
#pragma unroll
    for (int st = 128; st > 0; st >>= 1) {
        if (tid < st) red[tid] += red[tid + st];
        __syncthreads();
    }
    float mu = red[0] * (1.f / 256.f);
    __syncthreads();
    float dv = v - mu;
    red[tid] = dv * dv; __syncthreads();
#pragma unroll
    for (int st = 128; st > 0; st >>= 1) {
        if (tid < st) red[tid] += red[tid + st];
        __syncthreads();
    }
    float var = red[0] * (1.f / 256.f);
    float y = lng[layer * HH + tid] * dv * rsqrtf(var + 1e-5f) + lnb[layer * HH + tid];
    float gv = geluf(y);
    float hn = (layer > 0) ? (gv + g_h[(size_t)n * HH + tid]) : gv;
    g_h[(size_t)n * HH + tid] = hn;
}

// ---------------- graph pooling (sorted batch -> ranges, no atomics) ----------------
__global__ void bounds_kernel(const int* __restrict__ batch) {
    int n = blockIdx.x * blockDim.x + threadIdx.x;
    if (n >= NN) return;
    int b = batch[n];
    if (n == 0 || batch[n - 1] != b) g_gs[b] = n;
    if (n == NN - 1 || batch[n + 1] != b) g_ge[b] = n + 1;
}

__global__ __launch_bounds__(256) void pool_kernel() {
    int g = blockIdx.x, t = threadIdx.x;
    int beg = g_gs[g], end = g_ge[g];
    float s = 0.f;
    for (int n = beg; n < end; n++) s += g_h[(size_t)n * HH + t];
    float cnt = (float)(end - beg);
    g_xg[g * 512 + t] = s / fmaxf(cnt, 1.f);
    g_xg[g * 512 + 256 + t] = s;
}

// ---------------- MLP heads ----------------
__global__ __launch_bounds__(256) void mlp_kernel(
    const float* __restrict__ pw1, const float* __restrict__ pb1,
    const float* __restrict__ pw2, const float* __restrict__ pb2,
    const float* __restrict__ pw3, const float* __restrict__ pb3,
    const float* __restrict__ mw1, const float* __restrict__ mb1,
    const float* __restrict__ mw2, const float* __restrict__ mb2,
    const float* __restrict__ mw3, const float* __restrict__ mb3,
    float* __restrict__ out) {
    int g = blockIdx.x & 15;
    int head = blockIdx.x >> 4;
    const float* w1 = head ? mw1 : pw1; const float* b1 = head ? mb1 : pb1;
    const float* w2 = head ? mw2 : pw2; const float* b2 = head ? mb2 : pb2;
    const float* w3 = head ? mw3 : pw3; const float* b3 = head ? mb3 : pb3;
    int t = threadIdx.x;
    __shared__ float sx[512];
    __shared__ float h1[256];
    __shared__ float h2[128];
    sx[t] = g_xg[g * 512 + t];
    sx[t + 256] = g_xg[g * 512 + 256 + t];
    __syncthreads();
    {
        const float* wr = w1 + (size_t)t * 512;
        float a = b1[t];
        for (int k = 0; k < 512; k++) a = fmaf(sx[k], wr[k], a);
        h1[t] = geluf(a);
    }
    __syncthreads();
    if (t < 128) {
        const float* wr = w2 + (size_t)t * 256;
        float a = b2[t];
        for (int k = 0; k < 256; k++) a = fmaf(h1[k], wr[k], a);
        h2[t] = geluf(a);
    }
    __syncthreads();
    if (t < 3) {
        const float* wr = w3 + (size_t)t * 128;
        float a = b3[t];
        for (int k = 0; k < 128; k++) a = fmaf(h2[k], wr[k], a);
        out[head * 48 + g * 3 + t] = 1.f / (1.f + expf(-a));
    }
}

// ---------------- launcher ----------------
extern "C" void kernel_launch(void* const* d_in, const int* in_sizes, int n_in,
                              void* d_out, int out_size) {
    const float* x          = (const float*)d_in[0];
    const int*   edge_index = (const int*)d_in[1];
    const float* edge_attr  = (const float*)d_in[2];
    const int*   batch      = (const int*)d_in[3];
    const float* node_w     = (const float*)d_in[4];
    const float* node_b     = (const float*)d_in[5];
    const float* eew        = (const float*)d_in[6];
    const float* eeb        = (const float*)d_in[7];
    const float* lin_w      = (const float*)d_in[8];
    const float* att_src    = (const float*)d_in[9];
    const float* att_dst    = (const float*)d_in[10];
    const float* att_edge   = (const float*)d_in[11];
    const float* lin_edge_w = (const float*)d_in[12];
    const float* conv_b     = (const float*)d_in[13];
    const float* ln_g       = (const float*)d_in[14];
    const float* ln_b       = (const float*)d_in[15];
    const float* pw1 = (const float*)d_in[16]; const float* pb1 = (const float*)d_in[17];
    const float* pw2 = (const float*)d_in[18]; const float* pb2 = (const float*)d_in[19];
    const float* pw3 = (const float*)d_in[20]; const float* pb3 = (const float*)d_in[21];
    const float* mw1 = (const float*)d_in[22]; const float* mb1 = (const float*)d_in[23];
    const float* mw2 = (const float*)d_in[24]; const float* mb2 = (const float*)d_in[25];
    const float* mw3 = (const float*)d_in[26]; const float* mb3 = (const float*)d_in[27];
    float* out = (float*)d_out;

    // setup
    zero_kernel<<<64, 256>>>();
    deg_kernel<<<(NE + 255) / 256, 256>>>(edge_index);
    scan_kernel<<<1, 1024>>>();
    fill_kernel<<<(NE + 255) / 256, 256>>>(edge_index);
    loopslot_kernel<<<(NN + 255) / 256, 256>>>();
    u_kernel<<<48, 256>>>(att_edge, lin_edge_w, eew, eeb);
    alphaP_kernel<<<(EN + 127) / 128, 128>>>(edge_attr);
    loopdiv_kernel<<<NN, 256>>>();
    bounds_kernel<<<(NN + 255) / 256, 256>>>(batch);

    float *d_h, *d_xw;
    cudaGetSymbolAddress((void**)&d_h, g_h);
    cudaGetSymbolAddress((void**)&d_xw, g_xw);

    // node embedding: h = x @ node_w^T + node_b
    {
        dim3 grid((NN + 127) / 128, 2);
        gemm_nt<<<grid, 256>>>(x, node_w, node_b, d_h, NN, 64);
    }

    for (int layer = 0; layer < NL; layer++) {
        dim3 grid((NN + 127) / 128, 2);
        gemm_nt<<<grid, 256>>>(d_h, lin_w + (size_t)layer * 65536, nullptr, d_xw, NN, 256);
        asrc_kernel<<<(NN * NHD + 255) / 256, 256>>>(layer, att_src, att_dst);
        agg_kernel<<<NN, 256>>>(layer, conv_b, ln_g, ln_b);
    }

    pool_kernel<<<NG, 256>>>();
    mlp_kernel<<<32, 256>>>(pw1, pb1, pw2, pb2, pw3, pb3,
                            mw1, mb1, mw2, mb2, mw3, mb3, out);
}

// round 17
// speedup vs baseline: 2.1932x; 1.1382x over previous
#include <cuda_runtime.h>
#include <math.h>
#include <stdint.h>

#define NN 10000
#define NE 320000
#define EN 330000   // NE + NN self-loop slots
#define HH 256
#define NL 6
#define NHD 8
#define NG 16
#define DCAP 128    // per-warp smem alpha cache capacity

// ---------------- static device scratch ----------------
__device__ float g_h[NN * HH];
__device__ float g_xw[NN * HH];
__device__ float g_asrc[NN * NHD];
__device__ float g_adst[NN * NHD];
__device__ float g_alphaP[48 * EN];   // [layer*8+head][csr pos]
__device__ float g_u[48 * 32];
__device__ float g_uc[48];
__device__ int   g_deg[NN];
__device__ int   g_fill[NN];
__device__ int   g_off[NN + 1];
__device__ int   g_csrc[EN];
__device__ int   g_peid[EN];
__device__ int   g_gs[NG], g_ge[NG];
__device__ float g_xg[NG * 2 * HH];   // [g][mean(256) | sum(256)]

__device__ __forceinline__ float geluf(float x) {
    return 0.5f * x * (1.0f + erff(x * 0.70710678118654752f));
}

__device__ __forceinline__ uint32_t f2tf(float f) {
    uint32_t r;
    asm("cvt.rna.tf32.f32 %0, %1;" : "=r"(r) : "f"(f));
    return r;
}

// ---------------- zero accumulators ----------------
__global__ void zero_kernel() {
    int i = blockIdx.x * blockDim.x + threadIdx.x;
    int stride = gridDim.x * blockDim.x;
    for (int j = i; j < NN; j += stride) { g_deg[j] = 0; g_fill[j] = 0; }
    if (i < NG) { g_gs[i] = 0; g_ge[i] = 0; }
}

// ---------------- CSR build (by destination) ----------------
__global__ void deg_kernel(const int* __restrict__ ei) {
    int e = blockIdx.x * blockDim.x + threadIdx.x;
    if (e < NE) atomicAdd(&g_deg[ei[NE + e]], 1);
}

__global__ void scan_kernel() {
    __shared__ int s[1024];
    int t = threadIdx.x;
    int d[10];
    int loc = 0;
#pragma unroll
    for (int j = 0; j < 10; j++) {
        int n = t * 10 + j;
        int v = (n < NN) ? (g_deg[n] + 1) : 0;   // +1 self-loop slot
        d[j] = v; loc += v;
    }
    s[t] = loc; __syncthreads();
    for (int off = 1; off < 1024; off <<= 1) {
        int v = (t >= off) ? s[t - off] : 0;
        __syncthreads();
        s[t] += v;
        __syncthreads();
    }
    int ex = s[t] - loc;
#pragma unroll
    for (int j = 0; j < 10; j++) {
        int n = t * 10 + j;
        if (n < NN) g_off[n] = ex;
        ex += d[j];
    }
    if (t == 1023) g_off[NN] = s[1023];
}

__global__ void fill_kernel(const int* __restrict__ ei) {
    int e = blockIdx.x * blockDim.x + threadIdx.x;
    if (e >= NE) return;
    int d = ei[NE + e];
    int pos = g_off[d] + atomicAdd(&g_fill[d], 1);
    g_csrc[pos] = ei[e];
    g_peid[pos] = e;
}

__global__ void loopslot_kernel() {
    int n = blockIdx.x * blockDim.x + threadIdx.x;
    if (n >= NN) return;
    int pos = g_off[n + 1] - 1;
    g_csrc[pos] = n;
    g_peid[pos] = NE + n;
}

// ------- contracted edge weights: u[i,h,f] = ((att_edge slice @ lin_edge_w slice) @ eew) -------
__global__ void u_kernel(const float* __restrict__ att_edge,
                         const float* __restrict__ lin_edge_w,
                         const float* __restrict__ eew,
                         const float* __restrict__ eeb) {
    int comb = blockIdx.x;          // layer*8 + head
    int i = comb >> 3, hd = comb & 7;
    int tid = threadIdx.x;          // 256 threads
    __shared__ float sae[32];
    __shared__ float sv[256];
    if (tid < 32) sae[tid] = att_edge[i * 256 + hd * 32 + tid];
    __syncthreads();
    const float* lw = lin_edge_w + (size_t)i * 65536 + (size_t)(hd * 32) * 256 + tid;
    float v = 0.f;
#pragma unroll
    for (int o = 0; o < 32; o++) v = fmaf(sae[o], lw[(size_t)o * 256], v);
    sv[tid] = v; __syncthreads();
    if (tid < 32) {
        float u = 0.f;
        for (int c = 0; c < 256; c++) u = fmaf(sv[c], eew[c * 32 + tid], u);
        g_u[comb * 32 + tid] = u;
    }
    if (tid == 255) {
        float s = 0.f;
        for (int c = 0; c < 256; c++) s = fmaf(sv[c], eeb[c], s);
        g_uc[comb] = s;
    }
}

// ------- per-edge attr attention term for all 48 (layer,head) in CSR order -------
__global__ __launch_bounds__(128) void alphaP_kernel(const float* __restrict__ edge_attr) {
    __shared__ float su[48 * 32];
    __shared__ float suc[48];
    int tid = threadIdx.x;
    for (int j = tid; j < 48 * 32; j += 128) su[j] = g_u[j];
    if (tid < 48) suc[tid] = g_uc[tid];
    __syncthreads();
    int pos = blockIdx.x * 128 + tid;
    if (pos >= EN) return;
    int e = g_peid[pos];
    if (e >= NE) return;          // self-loop slot written by loopdiv_kernel
    float ea[32];
    const float4* p = (const float4*)(edge_attr + (size_t)e * 32);
#pragma unroll
    for (int q = 0; q < 8; q++) {
        float4 v = p[q];
        ea[4 * q] = v.x; ea[4 * q + 1] = v.y; ea[4 * q + 2] = v.z; ea[4 * q + 3] = v.w;
    }
#pragma unroll 2
    for (int c = 0; c < 48; c++) {
        const float4* u4 = (const float4*)&su[c * 32];
        float a0 = suc[c], a1 = 0.f, a2 = 0.f, a3 = 0.f;
#pragma unroll
        for (int q = 0; q < 8; q++) {
            float4 uu = u4[q];
            a0 = fmaf(ea[4 * q], uu.x, a0);
            a1 = fmaf(ea[4 * q + 1], uu.y, a1);
            a2 = fmaf(ea[4 * q + 2], uu.z, a2);
            a3 = fmaf(ea[4 * q + 3], uu.w, a3);
        }
        g_alphaP[(size_t)c * EN + pos] = (a0 + a1) + (a2 + a3);
    }
}

// ------- self-loop 'mean' slot: segment mean of alphaP over incoming edges (no atomics) -------
__global__ __launch_bounds__(256) void loopdiv_kernel() {
    int n = blockIdx.x;
    int wid = threadIdx.x >> 5, lane = threadIdx.x & 31;
    int beg = g_off[n], last = g_off[n + 1] - 1;   // [beg,last) are real edges
    float invc = 1.f / fmaxf((float)(last - beg), 1.f);
    for (int c = wid; c < 48; c += 8) {
        const float* ap = g_alphaP + (size_t)c * EN;
        float s = 0.f;
        for (int j = beg + lane; j < last; j += 32) s += ap[j];
#pragma unroll
        for (int o = 16; o > 0; o >>= 1) s += __shfl_xor_sync(0xffffffffu, s, o);
        if (lane == 0) g_alphaP[(size_t)c * EN + last] = s * invc;
    }
}

// ---------------- tf32 tensor-core GEMM: C[M,256] = A[M,K] @ B[256,K]^T (+bias) ----------------
// Epilogue optionally computes per-(row,head) attention scalars from the accumulator
// fragments (each warp's 32-column tile == one head) and writes g_asrc/g_adst.
__global__ __launch_bounds__(256) void gemm_nt(const float* __restrict__ A,
                                               const float* __restrict__ B,
                                               const float* __restrict__ bias,
                                               float* __restrict__ C,
                                               int M, int K,
                                               const float* __restrict__ attS,
                                               const float* __restrict__ attD,
                                               int layer) {
    __shared__ uint32_t As2[128 * 36];
    __shared__ uint32_t Bs2[128 * 36];
    int mBase = blockIdx.x * 128, nBase = blockIdx.y * 128;
    int tid = threadIdx.x;
    int warpId = tid >> 5, lane = tid & 31;
    int wm = warpId & 1, wn = warpId >> 1;        // 2 x 4 warp grid
    int g = lane >> 2, tig = lane & 3;

    float c[4][4][4];                              // [mt][nt][frag]
#pragma unroll
    for (int mt = 0; mt < 4; mt++)
#pragma unroll
        for (int nt = 0; nt < 4; nt++)
#pragma unroll
            for (int q = 0; q < 4; q++) c[mt][nt][q] = 0.f;

    for (int kb = 0; kb < K; kb += 32) {
#pragma unroll
        for (int i = 0; i < 4; i++) {
            int id = tid + i * 256;
            int row = id >> 3;
            int kc = (id & 7) << 2;
            float4 v = make_float4(0.f, 0.f, 0.f, 0.f);
            int gm = mBase + row;
            if (gm < M) v = *(const float4*)(A + (size_t)gm * K + kb + kc);
            uint4 t = make_uint4(f2tf(v.x), f2tf(v.y), f2tf(v.z), f2tf(v.w));
            *(uint4*)&As2[row * 36 + kc] = t;
        }
#pragma unroll
        for (int i = 0; i < 4; i++) {
            int id = tid + i * 256;
            int row = id >> 3;
            int kc = (id & 7) << 2;
            float4 v = *(const float4*)(B + (size_t)(nBase + row) * K + kb + kc);
            uint4 t = make_uint4(f2tf(v.x), f2tf(v.y), f2tf(v.z), f2tf(v.w));
            *(uint4*)&Bs2[row * 36 + kc] = t;
        }
        __syncthreads();

#pragma unroll
        for (int k8 = 0; k8 < 4; k8++) {
            int k0 = k8 * 8;
            uint32_t a[4][4], b[4][2];
#pragma unroll
            for (int mt = 0; mt < 4; mt++) {
                int r0 = (wm * 64 + mt * 16 + g) * 36;
                int r1 = (wm * 64 + mt * 16 + 8 + g) * 36;
                a[mt][0] = As2[r0 + k0 + tig];
                a[mt][1] = As2[r1 + k0 + tig];
                a[mt][2] = As2[r0 + k0 + tig + 4];
                a[mt][3] = As2[r1 + k0 + tig + 4];
            }
#pragma unroll
            for (int nt = 0; nt < 4; nt++) {
                int rn = (wn * 32 + nt * 8 + g) * 36;
                b[nt][0] = Bs2[rn + k0 + tig];
                b[nt][1] = Bs2[rn + k0 + tig + 4];
            }
#pragma unroll
            for (int mt = 0; mt < 4; mt++)
#pragma unroll
                for (int nt = 0; nt < 4; nt++) {
                    asm volatile(
                        "mma.sync.aligned.m16n8k8.row.col.f32.tf32.tf32.f32 "
                        "{%0,%1,%2,%3}, {%4,%5,%6,%7}, {%8,%9}, {%0,%1,%2,%3};"
                        : "+f"(c[mt][nt][0]), "+f"(c[mt][nt][1]),
                          "+f"(c[mt][nt][2]), "+f"(c[mt][nt][3])
                        : "r"(a[mt][0]), "r"(a[mt][1]), "r"(a[mt][2]), "r"(a[mt][3]),
                          "r"(b[nt][0]), "r"(b[nt][1]));
                }
        }
        __syncthreads();
    }

    // attention-scalar weights for this warp's head (32-column tile)
    int hd = (nBase + wn * 32) >> 5;
    float aSv[4][2], aDv[4][2];
    if (attS) {
#pragma unroll
        for (int nt = 0; nt < 4; nt++) {
            int cn = nBase + wn * 32 + nt * 8 + 2 * tig;
            aSv[nt][0] = attS[layer * 256 + cn];
            aSv[nt][1] = attS[layer * 256 + cn + 1];
            aDv[nt][0] = attD[layer * 256 + cn];
            aDv[nt][1] = attD[layer * 256 + cn + 1];
        }
    }

#pragma unroll
    for (int mt = 0; mt < 4; mt++) {
        int r0 = mBase + wm * 64 + mt * 16 + g;
        int r1 = r0 + 8;
#pragma unroll
        for (int nt = 0; nt < 4; nt++) {
            int cn = nBase + wn * 32 + nt * 8 + 2 * tig;
            float b0 = 0.f, b1 = 0.f;
            if (bias) { b0 = bias[cn]; b1 = bias[cn + 1]; }
            if (r0 < M) {
                float2 v = make_float2(c[mt][nt][0] + b0, c[mt][nt][1] + b1);
                *(float2*)(C + (size_t)r0 * HH + cn) = v;
            }
            if (r1 < M) {
                float2 v = make_float2(c[mt][nt][2] + b0, c[mt][nt][3] + b1);
                *(float2*)(C + (size_t)r1 * HH + cn) = v;
            }
        }
        if (attS) {
            // per-row head scalars: reduce over this thread's 8 cols then over tig group
            float s0 = 0.f, d0 = 0.f, s1 = 0.f, d1 = 0.f;
#pragma unroll
            for (int nt = 0; nt < 4; nt++) {
                s0 = fmaf(c[mt][nt][0], aSv[nt][0], fmaf(c[mt][nt][1], aSv[nt][1], s0));
                d0 = fmaf(c[mt][nt][0], aDv[nt][0], fmaf(c[mt][nt][1], aDv[nt][1], d0));
                s1 = fmaf(c[mt][nt][2], aSv[nt][0], fmaf(c[mt][nt][3], aSv[nt][1], s1));
                d1 = fmaf(c[mt][nt][2], aDv[nt][0], fmaf(c[mt][nt][3], aDv[nt][1], d1));
            }
#pragma unroll
            for (int o = 1; o < 4; o <<= 1) {
                s0 += __shfl_xor_sync(0xffffffffu, s0, o);
                d0 += __shfl_xor_sync(0xffffffffu, d0, o);
                s1 += __shfl_xor_sync(0xffffffffu, s1, o);
                d1 += __shfl_xor_sync(0xffffffffu, d1, o);
            }
            if (tig == 0) {
                if (r0 < M) { g_asrc[r0 * NHD + hd] = s0; g_adst[r0 * NHD + hd] = d0; }
                if (r1 < M) { g_asrc[r1 * NHD + hd] = s1; g_adst[r1 * NHD + hd] = d1; }
            }
        }
    }
}

// --------- fused alpha + softmax + aggregate + bias + LayerNorm + GELU + residual ---------
__global__ __launch_bounds__(256) void agg_kernel(int layer,
                                                  const float* __restrict__ convb,
                                                  const float* __restrict__ lng,
                                                  const float* __restrict__ lnb) {
    __shared__ float sbuf[NHD][DCAP];
    __shared__ int   s_src[DCAP];
    __shared__ float red[256];
    int n = blockIdx.x, tid = threadIdx.x;
    int hd = tid >> 5, lane = tid & 31;
    int beg = g_off[n], end = g_off[n + 1];
    int deg = end - beg;

    float s = 0.f, acc = 0.f;
    const float* xwp = g_xw + hd * 32 + lane;

    if (deg <= DCAP) {
        if (tid < deg) {
            int j = beg + tid;
            int src = g_csrc[j];
            s_src[tid] = src;
            const float4* sa = (const float4*)(g_asrc + (size_t)src * 8);
            const float4* da = (const float4*)(g_adst + (size_t)n * 8);
            float4 s0 = sa[0], s1 = sa[1], d0 = da[0], d1 = da[1];
            float as[8] = {s0.x, s0.y, s0.z, s0.w, s1.x, s1.y, s1.z, s1.w};
            float ad[8] = {d0.x, d0.y, d0.z, d0.w, d1.x, d1.y, d1.z, d1.w};
#pragma unroll
            for (int h = 0; h < 8; h++) {
                float a = as[h] + ad[h] + g_alphaP[(size_t)(layer * 8 + h) * EN + j];
                a = a > 0.f ? a : 0.2f * a;
                sbuf[h][tid] = a;
            }
        }
        __syncthreads();

        float m = -3.0e38f;
        for (int o = lane; o < deg; o += 32) m = fmaxf(m, sbuf[hd][o]);
#pragma unroll
        for (int o = 16; o > 0; o >>= 1) m = fmaxf(m, __shfl_xor_sync(0xffffffffu, m, o));

        for (int o = 0; o < deg; o++) {
            float e = __expf(sbuf[hd][o] - m);
            int src = s_src[o];
            s += e;
            acc = fmaf(e, xwp[(size_t)src * HH], acc);
        }
    } else {
        const float* aP = g_alphaP + (size_t)(layer * 8 + hd) * EN;
        float adst = g_adst[n * NHD + hd];
        float m = -3.0e38f;
        for (int j = beg + lane; j < end; j += 32) {
            float a = g_asrc[(size_t)g_csrc[j] * NHD + hd] + adst + aP[j];
            a = a > 0.f ? a : 0.2f * a;
            m = fmaxf(m, a);
        }
#pragma unroll
        for (int o = 16; o > 0; o >>= 1) m = fmaxf(m, __shfl_xor_sync(0xffffffffu, m, o));
        for (int j = beg; j < end; j++) {
            int src = g_csrc[j];
            float a = g_asrc[(size_t)src * NHD + hd] + adst + aP[j];
            a = a > 0.f ? a : 0.2f * a;
            float e = __expf(a - m);
            s += e;
            acc = fmaf(e, xwp[(size_t)src * HH], acc);
        }
    }
    acc *= 1.f / (s + 1e-16f);

    float v = acc + convb[layer * HH + tid];
    red[tid] = v; __syncthreads();
#pragma unroll
    for (int st = 128; st > 0; st >>= 1) {
        if (tid < st) red[tid] += red[tid + st];
        __syncthreads();
    }
    float mu = red[0] * (1.f / 256.f);
    __syncthreads();
    float dv = v - mu;
    red[tid] = dv * dv; __syncthreads();
#pragma unroll
    for (int st = 128; st > 0; st >>= 1) {
        if (tid < st) red[tid] += red[tid + st];
        __syncthreads();
    }
    float var = red[0] * (1.f / 256.f);
    float y = lng[layer * HH + tid] * dv * rsqrtf(var + 1e-5f) + lnb[layer * HH + tid];
    float gv = geluf(y);
    float hn = (layer > 0) ? (gv + g_h[(size_t)n * HH + tid]) : gv;
    g_h[(size_t)n * HH + tid] = hn;
}

// ---------------- graph pooling (sorted batch -> ranges, no atomics) ----------------
__global__ void bounds_kernel(const int* __restrict__ batch) {
    int n = blockIdx.x * blockDim.x + threadIdx.x;
    if (n >= NN) return;
    int b = batch[n];
    if (n == 0 || batch[n - 1] != b) g_gs[b] = n;
    if (n == NN - 1 || batch[n + 1] != b) g_ge[b] = n + 1;
}

__global__ __launch_bounds__(256) void pool_kernel() {
    int g = blockIdx.x, t = threadIdx.x;
    int beg = g_gs[g], end = g_ge[g];
    float s = 0.f;
    for (int n = beg; n < end; n++) s += g_h[(size_t)n * HH + t];
    float cnt = (float)(end - beg);
    g_xg[g * 512 + t] = s / fmaxf(cnt, 1.f);
    g_xg[g * 512 + 256 + t] = s;
}

// ---------------- MLP heads ----------------
__global__ __launch_bounds__(256) void mlp_kernel(
    const float* __restrict__ pw1, const float* __restrict__ pb1,
    const float* __restrict__ pw2, const float* __restrict__ pb2,
    const float* __restrict__ pw3, const float* __restrict__ pb3,
    const float* __restrict__ mw1, const float* __restrict__ mb1,
    const float* __restrict__ mw2, const float* __restrict__ mb2,
    const float* __restrict__ mw3, const float* __restrict__ mb3,
    float* __restrict__ out) {
    int g = blockIdx.x & 15;
    int head = blockIdx.x >> 4;
    const float* w1 = head ? mw1 : pw1; const float* b1 = head ? mb1 : pb1;
    const float* w2 = head ? mw2 : pw2; const float* b2 = head ? mb2 : pb2;
    const float* w3 = head ? mw3 : pw3; const float* b3 = head ? mb3 : pb3;
    int t = threadIdx.x;
    __shared__ float sx[512];
    __shared__ float h1[256];
    __shared__ float h2[128];
    sx[t] = g_xg[g * 512 + t];
    sx[t + 256] = g_xg[g * 512 + 256 + t];
    __syncthreads();
    {
        const float* wr = w1 + (size_t)t * 512;
        float a = b1[t];
        for (int k = 0; k < 512; k++) a = fmaf(sx[k], wr[k], a);
        h1[t] = geluf(a);
    }
    __syncthreads();
    if (t < 128) {
        const float* wr = w2 + (size_t)t * 256;
        float a = b2[t];
        for (int k = 0; k < 256; k++) a = fmaf(h1[k], wr[k], a);
        h2[t] = geluf(a);
    }
    __syncthreads();
    if (t < 3) {
        const float* wr = w3 + (size_t)t * 128;
        float a = b3[t];
        for (int k = 0; k < 128; k++) a = fmaf(h2[k], wr[k], a);
        out[head * 48 + g * 3 + t] = 1.f / (1.f + expf(-a));
    }
}

// ---------------- launcher ----------------
extern "C" void kernel_launch(void* const* d_in, const int* in_sizes, int n_in,
                              void* d_out, int out_size) {
    const float* x          = (const float*)d_in[0];
    const int*   edge_index = (const int*)d_in[1];
    const float* edge_attr  = (const float*)d_in[2];
    const int*   batch      = (const int*)d_in[3];
    const float* node_w     = (const float*)d_in[4];
    const float* node_b     = (const float*)d_in[5];
    const float* eew        = (const float*)d_in[6];
    const float* eeb        = (const float*)d_in[7];
    const float* lin_w      = (const float*)d_in[8];
    const float* att_src    = (const float*)d_in[9];
    const float* att_dst    = (const float*)d_in[10];
    const float* att_edge   = (const float*)d_in[11];
    const float* lin_edge_w = (const float*)d_in[12];
    const float* conv_b     = (const float*)d_in[13];
    const float* ln_g       = (const float*)d_in[14];
    const float* ln_b       = (const float*)d_in[15];
    const float* pw1 = (const float*)d_in[16]; const float* pb1 = (const float*)d_in[17];
    const float* pw2 = (const float*)d_in[18]; const float* pb2 = (const float*)d_in[19];
    const float* pw3 = (const float*)d_in[20]; const float* pb3 = (const float*)d_in[21];
    const float* mw1 = (const float*)d_in[22]; const float* mb1 = (const float*)d_in[23];
    const float* mw2 = (const float*)d_in[24]; const float* mb2 = (const float*)d_in[25];
    const float* mw3 = (const float*)d_in[26]; const float* mb3 = (const float*)d_in[27];
    float* out = (float*)d_out;

    // setup
    zero_kernel<<<64, 256>>>();
    deg_kernel<<<(NE + 255) / 256, 256>>>(edge_index);
    scan_kernel<<<1, 1024>>>();
    fill_kernel<<<(NE + 255) / 256, 256>>>(edge_index);
    loopslot_kernel<<<(NN + 255) / 256, 256>>>();
    u_kernel<<<48, 256>>>(att_edge, lin_edge_w, eew, eeb);
    alphaP_kernel<<<(EN + 127) / 128, 128>>>(edge_attr);
    loopdiv_kernel<<<NN, 256>>>();
    bounds_kernel<<<(NN + 255) / 256, 256>>>(batch);

    float *d_h, *d_xw;
    cudaGetSymbolAddress((void**)&d_h, g_h);
    cudaGetSymbolAddress((void**)&d_xw, g_xw);

    // node embedding: h = x @ node_w^T + node_b (no attention epilogue)
    {
        dim3 grid((NN + 127) / 128, 2);
        gemm_nt<<<grid, 256>>>(x, node_w, node_b, d_h, NN, 64, nullptr, nullptr, 0);
    }

    for (int layer = 0; layer < NL; layer++) {
        dim3 grid((NN + 127) / 128, 2);
        gemm_nt<<<grid, 256>>>(d_h, lin_w + (size_t)layer * 65536, nullptr, d_xw, NN, 256,
                               att_src, att_dst, layer);
        agg_kernel<<<NN, 256>>>(layer, conv_b, ln_g, ln_b);
    }

    pool_kernel<<<NG, 256>>>();
    mlp_kernel<<<32, 256>>>(pw1, pb1, pw2, pb2, pw3, pb3,
                            mw1, mb1, mw2, mb2, mw3, mb3, out);
}